// round 10
// baseline (speedup 1.0000x reference)
#include <cuda_runtime.h>
#include <cstdint>

#define DIMC 512
#define EE 336
#define E3 1008
#define NSTATE 16
#define NH 6
#define HDIM 56
#define BB 8
#define LL 4096
#define NN (BB*LL)        // 32768 tokens
#define KC 819
#define DU 64             // truncated scan kernel length
#define DK 67             // combined (scan * dconv) kernel length

// weight plane offsets (floats) — transposed [n][k] layout, same sizes
#define OFF_WIN  0
#define OFF_WQKV (512*336)
#define OFF_WOUT (512*336 + 336*1008)
#define WPL_TOTAL (512*336 + 336*1008 + 336*512)

// ---------------- scratch (static device memory; no allocs allowed) ----------
__device__ float g_xp[(size_t)NN*EE];
__device__ float g_qkv[(size_t)NN*E3];
__device__ float g_att[(size_t)NN*EE];
__device__ float g_imp[NN];
__device__ int   g_idx[BB*KC];
__device__ float g_xproc[(size_t)BB*KC*DIMC];
__device__ float g_K[EE*DK];
__device__ float g_Wh[WPL_TOTAL];          // W^T hi plane, k-interleaved
__device__ float g_Wl[WPL_TOTAL];          // W^T lo plane
__device__ float g_xph[(size_t)NN*EE];     // xpn hi plane (k-interleaved)
__device__ float g_xpl[(size_t)NN*EE];
__device__ float g_ysh[(size_t)BB*KC*EE];  // ys hi plane (k-interleaved)
__device__ float g_ysl[(size_t)BB*KC*EE];

// ============================ helpers =======================================
__device__ __forceinline__ uint32_t smem_u32(const void* p) {
    uint32_t a;
    asm("{ .reg .u64 t; cvta.to.shared.u64 t, %1; cvt.u32.u64 %0, t; }" : "=r"(a) : "l"(p));
    return a;
}
__device__ __forceinline__ void tf32_split(float v, uint32_t& h, uint32_t& l) {
    uint32_t hb; asm("cvt.rna.tf32.f32 %0, %1;" : "=r"(hb) : "f"(v));
    float hf = __uint_as_float(hb);
    uint32_t lb; asm("cvt.rna.tf32.f32 %0, %1;" : "=r"(lb) : "f"(v - hf));
    h = hb; l = lb;
}
// storage position of element k within its 8-block (pair-interleave for LDS.64)
__device__ __forceinline__ int kpos(int k) {
    int c = k & 7;
    return (k & ~7) + ((c < 4) ? (c << 1) : (((c - 4) << 1) | 1));
}
__device__ __forceinline__ void mma8(float* c, uint32_t a0, uint32_t a1,
                                     uint32_t a2, uint32_t a3,
                                     uint32_t b0, uint32_t b1) {
    asm volatile("mma.sync.aligned.m16n8k8.row.col.f32.tf32.tf32.f32 "
        "{%0,%1,%2,%3}, {%4,%5,%6,%7}, {%8,%9}, {%0,%1,%2,%3};"
        : "+f"(c[0]), "+f"(c[1]), "+f"(c[2]), "+f"(c[3])
        : "r"(a0), "r"(a1), "r"(a2), "r"(a3), "r"(b0), "r"(b1));
}
__device__ __forceinline__ void cpa16(uint32_t dst, const void* src, uint32_t sz) {
    asm volatile("cp.async.ca.shared.global [%0], [%1], 16, %2;"
        :: "r"(dst), "l"(src), "r"(sz));
}

// ------- weight split: W[K,N] -> W^T hi/lo planes [n][kpos(k)] (tiled) -------
__global__ void wsplit_t_kernel(const float* __restrict__ W0,
                                const float* __restrict__ W1,
                                const float* __restrict__ W2,
                                float* __restrict__ Wh, float* __restrict__ Wl)
{
    __shared__ float t[32][33];
    int z = blockIdx.z;
    const float* W = (z == 0) ? W0 : ((z == 1) ? W1 : W2);
    int K = (z == 0) ? 512 : 336;
    int N = (z == 0) ? 336 : ((z == 1) ? 1008 : 512);
    int off = (z == 0) ? OFF_WIN : ((z == 1) ? OFF_WQKV : OFF_WOUT);
    int k0 = blockIdx.x * 32, n0 = blockIdx.y * 32;
    if (k0 >= K || n0 >= N) return;
    int tx = threadIdx.x, ty = threadIdx.y;   // (32, 8)
    #pragma unroll
    for (int i = 0; i < 4; i++) {
        int k = k0 + ty + i * 8, n = n0 + tx;
        if (k < K && n < N) t[ty + i*8][tx] = W[(size_t)k * N + n];
    }
    __syncthreads();
    #pragma unroll
    for (int i = 0; i < 4; i++) {
        int n = n0 + ty + i * 8, k = k0 + tx;
        if (k < K && n < N) {
            uint32_t h, l;
            tf32_split(t[tx][ty + i*8], h, l);
            size_t o = (size_t)off + (size_t)n * K + kpos(k);
            Wh[o] = __uint_as_float(h);
            Wl[o] = __uint_as_float(l);
        }
    }
}

// ================== split-tf32 (3-pass) warp-MMA GEMM =======================
// C[M,N] = op(A)[M,K] @ W[K,N] + bias.  K-chunk 32, 2-stage cp.async.
// 8 warps as 2M x 4N; warp tile 64 x (BN/4); LDS.64 fragment loads via
// k-interleaved SMEM layouts (A planes [r][kpos], B planes [n][kpos]).
// MODE 1: A raw fp32 streamed, DyT+split transform in-kernel.
// MODE 0: A pre-split planes streamed directly.
template<int BN, int MODE>
__global__ void __launch_bounds__(256, 1) mma_gemm(
    const float* __restrict__ A,
    const float* __restrict__ Ahg, const float* __restrict__ Alg,
    const float* __restrict__ Wh, const float* __restrict__ Wl,
    const float* __restrict__ bias, float* __restrict__ C,
    int M, int N, int K,
    const float* __restrict__ alpha, const float* __restrict__ dw,
    const float* __restrict__ db)
{
    constexpr int PA = 40;            // A pitch (words): conflict-free LDS.64
    constexpr int PK = 40;            // B pitch (words): conflict-free LDS.64
    constexpr int NT8 = BN / 32;      // n8 tiles per warp (6 or 7)
    constexpr int WN = BN / 4;
    constexpr int PRAW = 36;          // raw A pitch (MODE1)
    constexpr int AST = (MODE == 0) ? 2 : 1;

    extern __shared__ uint32_t smw[];
    // MODE1: rawA[2][128*PRAW] | AhP[128*PA] | AlP[128*PA] | Bh[2][BN*PK] | Bl[2][BN*PK]
    // MODE0: AhP[2][128*PA] | AlP[2][128*PA] | Bh[2][BN*PK] | Bl[2][BN*PK]
    uint32_t* rawA = smw;
    uint32_t* AhP  = smw + ((MODE == 1) ? 2 * 128 * PRAW : 0);
    uint32_t* AlP  = AhP + AST * 128 * PA;
    uint32_t* BhP  = AlP + AST * 128 * PA;
    uint32_t* BlP  = BhP + 2 * BN * PK;

    uint32_t sbase  = smem_u32(smw);
    uint32_t rawA_b = sbase;
    uint32_t AhP_b  = sbase + (uint32_t)(((MODE == 1) ? 2*128*PRAW : 0) * 4);
    uint32_t AlP_b  = AhP_b + (uint32_t)(AST * 128 * PA * 4);
    uint32_t BhP_b  = AlP_b + (uint32_t)(AST * 128 * PA * 4);
    uint32_t BlP_b  = BhP_b + (uint32_t)(2 * BN * PK * 4);

    int tid = threadIdx.x, wid = tid >> 5, lane = tid & 31;
    int wm = (wid & 1) * 64, wn = (wid >> 1) * WN;
    int g4 = lane >> 2, t4 = lane & 3;
    int m0 = blockIdx.y * 128, n0 = blockIdx.x * BN;
    float a0s = (MODE == 1) ? __ldg(alpha) : 0.f;

    float acc[4][NT8][4];
    #pragma unroll
    for (int i = 0; i < 4; i++)
        #pragma unroll
        for (int j = 0; j < NT8; j++)
            #pragma unroll
            for (int t = 0; t < 4; t++) acc[i][j][t] = 0.f;

    int NC = (K + 31) / 32;

    // ---- async issue of chunk c into stage c&1
    auto issue = [&](int c) {
        int s = c & 1;
        int k0 = c * 32;
        #pragma unroll
        for (int it = 0; it < 4; it++) {
            int idx = tid + it * 256;        // 1024 A groups
            int r = idx >> 3, f4 = idx & 7;
            int gm = m0 + r, gk = k0 + f4 * 4;
            bool v = (gm < M) && (gk < K);
            size_t go = (size_t)gm * K + gk;
            if (MODE == 1) {
                cpa16(rawA_b + (uint32_t)((s*128*PRAW + r*PRAW + f4*4) * 4),
                      v ? (A + go) : A, v ? 16u : 0u);
            } else {
                uint32_t so = (uint32_t)((s*128*PA + r*PA + f4*4) * 4);
                cpa16(AhP_b + so, v ? (Ahg + go) : Ahg, v ? 16u : 0u);
                cpa16(AlP_b + so, v ? (Alg + go) : Alg, v ? 16u : 0u);
            }
        }
        constexpr int BGRP = BN * 8;
        #pragma unroll
        for (int it = 0; it < (BGRP + 255) / 256; it++) {
            int idx = tid + it * 256;
            if (idx < BGRP) {
                int nr = idx >> 3, q = idx & 7;
                int gn = n0 + nr, gk = k0 + q * 4;
                bool v = (gn < N) && (gk < K);
                size_t go = (size_t)gn * K + gk;    // transposed planes [n][k]
                uint32_t so = (uint32_t)((s*BN*PK + nr*PK + q*4) * 4);
                cpa16(BhP_b + so, v ? (Wh + go) : Wh, v ? 16u : 0u);
                cpa16(BlP_b + so, v ? (Wl + go) : Wl, v ? 16u : 0u);
            }
        }
        asm volatile("cp.async.commit_group;" ::: "memory");
    };

    // ---- MODE1 only: raw A -> k-interleaved hi/lo planes with DyT fused
    auto transform = [&](int c) {
        int s = c & 1;
        int k0 = c * 32;
        #pragma unroll
        for (int it = 0; it < 4; it++) {
            int idx = tid + it * 256;
            int r = idx >> 3, f4 = idx & 7;
            float4 v = *(const float4*)(rawA + s * 128 * PRAW + r * PRAW + f4 * 4);
            int gk = k0 + f4 * 4;
            float4 w4 = *(const float4*)(dw + gk);
            float4 b4 = *(const float4*)(db + gk);
            v.x = tanhf(a0s * v.x) * w4.x + b4.x;
            v.y = tanhf(a0s * v.y) * w4.y + b4.y;
            v.z = tanhf(a0s * v.z) * w4.z + b4.z;
            v.w = tanhf(a0s * v.w) * w4.w + b4.w;
            // element j of this float4 has chunk-local k = f4*4+j,
            // stored at w = (f4>>1)*8 + j*2 + (f4&1)
            int wb = r * PA + ((f4 >> 1) << 3) + (f4 & 1);
            uint32_t h, l;
            tf32_split(v.x, h, l); AhP[wb + 0] = h; AlP[wb + 0] = l;
            tf32_split(v.y, h, l); AhP[wb + 2] = h; AlP[wb + 2] = l;
            tf32_split(v.z, h, l); AhP[wb + 4] = h; AlP[wb + 4] = l;
            tf32_split(v.w, h, l); AhP[wb + 6] = h; AlP[wb + 6] = l;
        }
    };

    // ---- pure LDS.64+MMA over one 32-wide K chunk (4 k8 steps)
    auto compute = [&](int c) {
        int s = c & 1;
        const uint32_t* Ahb = AhP + ((MODE == 0) ? s * 128 * PA : 0);
        const uint32_t* Alb = AlP + ((MODE == 0) ? s * 128 * PA : 0);
        const uint32_t* Bhb = BhP + s * BN * PK;
        const uint32_t* Blb = BlP + s * BN * PK;
        #pragma unroll
        for (int kk = 0; kk < 4; kk++) {
            int k2 = kk * 8 + t4 * 2;
            uint2 ah[4][2], al[4][2];   // [mt][rows r / r+8] = (col t4, col t4+4)
            #pragma unroll
            for (int mt = 0; mt < 4; mt++) {
                int r0 = (wm + mt * 16 + g4) * PA + k2;
                ah[mt][0] = *(const uint2*)(Ahb + r0);
                ah[mt][1] = *(const uint2*)(Ahb + r0 + 8 * PA);
                al[mt][0] = *(const uint2*)(Alb + r0);
                al[mt][1] = *(const uint2*)(Alb + r0 + 8 * PA);
            }
            uint2 bh[NT8], bl[NT8];
            #pragma unroll
            for (int nt = 0; nt < NT8; nt++) {
                int nb = (wn + nt * 8 + g4) * PK + k2;
                bh[nt] = *(const uint2*)(Bhb + nb);
                bl[nt] = *(const uint2*)(Blb + nb);
            }
            #pragma unroll
            for (int mt = 0; mt < 4; mt++)
                #pragma unroll
                for (int nt = 0; nt < NT8; nt++) {
                    mma8(acc[mt][nt], ah[mt][0].x, ah[mt][1].x, ah[mt][0].y, ah[mt][1].y,
                         bh[nt].x, bh[nt].y);
                    mma8(acc[mt][nt], ah[mt][0].x, ah[mt][1].x, ah[mt][0].y, ah[mt][1].y,
                         bl[nt].x, bl[nt].y);
                    mma8(acc[mt][nt], al[mt][0].x, al[mt][1].x, al[mt][0].y, al[mt][1].y,
                         bh[nt].x, bh[nt].y);
                }
        }
    };

    issue(0);
    for (int c = 0; c < NC; c++) {
        asm volatile("cp.async.wait_group 0;" ::: "memory");
        __syncthreads();                 // chunk c visible; prev compute done
        if (c + 1 < NC) issue(c + 1);    // overlaps transform/compute of chunk c
        if (MODE == 1) {
            transform(c);
            __syncthreads();
        }
        compute(c);
    }

    // ---- epilogue: registers -> global with bias
    #pragma unroll
    for (int mt = 0; mt < 4; mt++) {
        int gr = m0 + wm + mt * 16 + g4;
        #pragma unroll
        for (int nt = 0; nt < NT8; nt++) {
            int gc = n0 + wn + nt * 8 + t4 * 2;
            if (gc >= N) continue;
            float2 bv = *(const float2*)(bias + gc);
            if (gr < M) {
                float2 o = make_float2(acc[mt][nt][0] + bv.x, acc[mt][nt][1] + bv.y);
                *(float2*)(C + (size_t)gr * N + gc) = o;
            }
            if (gr + 8 < M) {
                float2 o = make_float2(acc[mt][nt][2] + bv.x, acc[mt][nt][3] + bv.y);
                *(float2*)(C + (size_t)(gr + 8) * N + gc) = o;
            }
        }
    }
}

// ---------------- prep: combined conv kernel --------------------------------
__global__ void prep_kernel(const float* __restrict__ A, const float* __restrict__ Bp,
                            const float* __restrict__ Cp, const float* __restrict__ cw)
{
    __shared__ float U[DU][NSTATE];
    __shared__ float gk[DU];
    __shared__ float sC[NSTATE];
    int tid = threadIdx.x;
    int e = blockIdx.x;
    if (tid < 32) {
        int i = tid & 15;
        float u = 1.f / (1.f + expf(-Bp[i]));
        for (int d = 0; d < DU; d++) {
            if (tid < 16) U[d][i] = u;
            float nu = 0.f;
            #pragma unroll
            for (int j = 0; j < 16; j++)
                nu += A[i*16 + j] * __shfl_sync(0xFFFFFFFFu, u, j);
            u = nu;
        }
    }
    if (tid < 16) sC[tid] = 1.f / (1.f + expf(-Cp[e*16 + tid]));
    __syncthreads();
    for (int d = tid; d < DU; d += blockDim.x) {
        float s = 0.f;
        #pragma unroll
        for (int i = 0; i < 16; i++) s += sC[i] * U[d][i];
        gk[d] = s;
    }
    __syncthreads();
    for (int dd = tid; dd < DK; dd += blockDim.x) {
        float s = 0.f;
        #pragma unroll
        for (int d1 = 0; d1 < 4; d1++) {
            int d2 = dd - d1;
            if (d2 >= 0 && d2 < DU) s += cw[e*4 + (3 - d1)] * gk[d2];
        }
        g_K[e*DK + dd] = s;
    }
}

// ---------- row L2-normalize -> pre-split, k-interleaved hi/lo planes -------
__global__ void norm_kernel(const float* __restrict__ xp,
                            float* __restrict__ xh, float* __restrict__ xl)
{
    int lane = threadIdx.x & 31;
    int row = blockIdx.x * 8 + (threadIdx.x >> 5);
    const float* p = xp + (size_t)row * EE;
    float s = 0.f;
    for (int e = lane; e < EE; e += 32) { float v = p[e]; s += v*v; }
    #pragma unroll
    for (int o = 16; o > 0; o >>= 1) s += __shfl_xor_sync(0xFFFFFFFFu, s, o);
    float inv = 1.f / fmaxf(sqrtf(s), 1e-12f);
    for (int e = lane; e < EE; e += 32) {
        float v = p[e] * inv;
        uint32_t h, l;
        tf32_split(v, h, l);
        size_t o = (size_t)row * EE + kpos(e);
        xh[o] = __uint_as_float(h);
        xl[o] = __uint_as_float(l);
    }
}

// ---------------- attention -------------------------------------------------
__global__ void attn_kernel(const float* __restrict__ qkv,
                            float* __restrict__ att, float* __restrict__ imp)
{
    __shared__ float sq[4][E3];
    __shared__ float sc[4][36];
    __shared__ int   gb[4][NH];
    int wid = threadIdx.x >> 5, lane = threadIdx.x & 31;
    int n = blockIdx.x * 4 + wid;
    const float* row = qkv + (size_t)n * E3;
    float* s = sq[wid];
    for (int e = lane; e < E3; e += 32) s[e] = row[e];
    __syncwarp();
    for (int p = lane; p < 36; p += 32) {
        int h = p / 6, g = p - h*6;
        const float* qp = s + h*HDIM;
        const float* kp = s + EE + g*HDIM;
        float d = 0.f;
        #pragma unroll
        for (int t = 0; t < HDIM; t++) d += qp[t] * kp[t];
        sc[wid][p] = d;
    }
    __syncwarp();
    if (lane < NH) {
        float best = sc[wid][lane*6]; int bg = 0;
        #pragma unroll
        for (int g = 1; g < 6; g++) {
            float v = sc[wid][lane*6 + g];
            if (v > best) { best = v; bg = g; }   // strict > : jax tie -> lowest idx
        }
        gb[wid][lane] = bg;
    }
    __syncwarp();
    float acc = 0.f;
    for (int e = lane; e < EE; e += 32) {
        int h = e % NH, d = e / NH;
        float v = s[2*EE + gb[wid][h]*HDIM + d];
        att[(size_t)n*EE + e] = v;
        acc += v*v;
    }
    #pragma unroll
    for (int o = 16; o > 0; o >>= 1) acc += __shfl_xor_sync(0xFFFFFFFFu, acc, o);
    if (lane == 0) imp[n] = sqrtf(acc);
}

// ---------------- top-819 per batch -----------------------------------------
__global__ void topk_kernel(const float* __restrict__ imp, int* __restrict__ idxout)
{
    __shared__ unsigned long long key[LL];
    int b = blockIdx.x;
    for (int i = threadIdx.x; i < LL; i += blockDim.x) {
        unsigned fb = __float_as_uint(imp[b*LL + i]);
        key[i] = ((unsigned long long)(0xFFFFFFFFu - fb) << 32) | (unsigned)i;
    }
    __syncthreads();
    for (int k = 2; k <= LL; k <<= 1)
        for (int j = k >> 1; j > 0; j >>= 1) {
            for (int i = threadIdx.x; i < LL; i += blockDim.x) {
                int ixj = i ^ j;
                if (ixj > i) {
                    bool up = ((i & k) == 0);
                    unsigned long long a = key[i], c = key[ixj];
                    if ((a > c) == up) { key[i] = c; key[ixj] = a; }
                }
            }
            __syncthreads();
        }
    for (int i = threadIdx.x; i < KC; i += blockDim.x)
        idxout[b*KC + i] = (int)(key[i] & 0xFFFFFFFFu);
}

// -------- fused gather + 67-tap causal conv -> k-interleaved ys planes ------
__global__ void __launch_bounds__(224) conv_kernel(const float* __restrict__ att,
                                                   const int* __restrict__ idx,
                                                   float* __restrict__ ysh,
                                                   float* __restrict__ ysl)
{
    const int ET = 56, JT = 64, WIN = JT + DK - 1;
    __shared__ float sp[ET][WIN + 1];
    __shared__ float Ks[ET][DK + 1];
    __shared__ int   sidx[WIN];
    int et = blockIdx.x, jt = blockIdx.y, b = blockIdx.z;
    int e0 = et * ET, j0 = jt * JT;
    int tid = threadIdx.x;

    for (int w = tid; w < WIN; w += 224) {
        int j = j0 - (DK - 1) + w;
        sidx[w] = (j >= 0 && j < KC) ? idx[b*KC + j] : -1;
    }
    for (int i = tid; i < ET*DK; i += 224) {
        int ee = i / DK, d = i - ee*DK;
        Ks[ee][d] = g_K[(e0 + ee)*DK + d];
    }
    __syncthreads();
    for (int i = tid; i < WIN*ET; i += 224) {
        int w = i / ET, ee = i - w*ET;
        int pos = sidx[w];
        sp[ee][w] = (pos >= 0) ? att[((size_t)b*LL + pos)*EE + e0 + ee] : 0.f;
    }
    __syncthreads();

    int ee = tid % ET, jg = tid / ET;
    float acc[16];
    #pragma unroll
    for (int t = 0; t < 16; t++) acc[t] = 0.f;
    int wbase = (DK - 1) + jg*16;
    for (int d = 0; d < DK; d++) {
        float kv = Ks[ee][d];
        #pragma unroll
        for (int t = 0; t < 16; t++)
            acc[t] += kv * sp[ee][wbase + t - d];
    }
    int ep = kpos(e0 + ee);
    #pragma unroll
    for (int t = 0; t < 16; t++) {
        int j = j0 + jg*16 + t;
        if (j < KC) {
            uint32_t h, l;
            tf32_split(acc[t], h, l);
            size_t o = ((size_t)b*KC + j)*EE + ep;
            ysh[o] = __uint_as_float(h);
            ysl[o] = __uint_as_float(l);
        }
    }
}

// ---------------- residual copy + scatter -----------------------------------
__global__ void residual_kernel(const float4* __restrict__ x, float4* __restrict__ out)
{
    size_t i = (size_t)blockIdx.x * blockDim.x + threadIdx.x;
    out[i] = x[i];
}

__global__ void scatter_kernel(const float* __restrict__ x, const float* __restrict__ xproc,
                               const int* __restrict__ idx, float* __restrict__ out)
{
    int row = blockIdx.x;
    int b = row / KC, j = row - b*KC;
    int pos = idx[b*KC + j];
    const float* xp = xproc + (size_t)row * DIMC;
    size_t base = ((size_t)b*LL + pos) * DIMC;
    for (int c = threadIdx.x; c < DIMC; c += blockDim.x)
        out[base + c] = x[base + c] + xp[c];
}

// ---------------- launch ----------------------------------------------------
extern "C" void kernel_launch(void* const* d_in, const int* in_sizes, int n_in,
                              void* d_out, int out_size)
{
    const float* x      = (const float*)d_in[0];
    const float* alpha  = (const float*)d_in[1];
    const float* dyt_w  = (const float*)d_in[2];
    const float* dyt_b  = (const float*)d_in[3];
    const float* W_in   = (const float*)d_in[4];
    const float* b_in   = (const float*)d_in[5];
    const float* W_qkv  = (const float*)d_in[6];
    const float* b_qkv  = (const float*)d_in[7];
    const float* conv_w = (const float*)d_in[8];
    const float* A      = (const float*)d_in[9];
    const float* Bp     = (const float*)d_in[10];
    const float* Cp     = (const float*)d_in[11];
    const float* W_out  = (const float*)d_in[12];
    const float* b_out  = (const float*)d_in[13];
    float* out = (float*)d_out;

    float *xp, *qkv, *att, *imp, *xproc, *wh, *wl, *xph, *xpl, *ysh, *ysl;
    int *idx;
    cudaGetSymbolAddress((void**)&xp,    g_xp);
    cudaGetSymbolAddress((void**)&qkv,   g_qkv);
    cudaGetSymbolAddress((void**)&att,   g_att);
    cudaGetSymbolAddress((void**)&imp,   g_imp);
    cudaGetSymbolAddress((void**)&idx,   g_idx);
    cudaGetSymbolAddress((void**)&xproc, g_xproc);
    cudaGetSymbolAddress((void**)&wh,    g_Wh);
    cudaGetSymbolAddress((void**)&wl,    g_Wl);
    cudaGetSymbolAddress((void**)&xph,   g_xph);
    cudaGetSymbolAddress((void**)&xpl,   g_xpl);
    cudaGetSymbolAddress((void**)&ysh,   g_ysh);
    cudaGetSymbolAddress((void**)&ysl,   g_ysl);

    // smem (bytes):
    // MODE1 BN=192: rawA 2*128*36 + planes 2*128*40 + B 2*2*192*40 = 50176 w = 200704
    // MODE0 BN=224: A 2*2*128*40 + B 2*2*224*40 = 56320 w = 225280
    // MODE0 BN=192: A 20480 + B 30720 = 51200 w = 204800
    const int SM_G1 = (2*128*36 + 2*128*40 + 2*2*192*40) * 4;
    const int SM_QK = (2*2*128*40 + 2*2*224*40) * 4;
    const int SM_G3 = (2*2*128*40 + 2*2*192*40) * 4;
    cudaFuncSetAttribute(mma_gemm<192,1>, cudaFuncAttributeMaxDynamicSharedMemorySize, SM_G1);
    cudaFuncSetAttribute(mma_gemm<224,0>, cudaFuncAttributeMaxDynamicSharedMemorySize, SM_QK);
    cudaFuncSetAttribute(mma_gemm<192,0>, cudaFuncAttributeMaxDynamicSharedMemorySize, SM_G3);

    // launch order: qkv GEMM lands at 0-based index 3 (ncu capture slot)
    // 0) all weight planes: transpose + split + k-interleave
    wsplit_t_kernel<<<dim3(16, 32, 3), dim3(32, 8)>>>(W_in, W_qkv, W_out, wh, wl);
    // 1) xp = dyt(x) @ W_in + b_in   [32768,512]x[512,336]  (MODE1)
    mma_gemm<192,1><<<dim3(2, NN/128), 256, SM_G1>>>(x, nullptr, nullptr,
                                                     wh + OFF_WIN, wl + OFF_WIN,
                                                     b_in, xp, NN, EE, DIMC,
                                                     alpha, dyt_w, dyt_b);
    // 2) row-normalize -> pre-split xpn planes
    norm_kernel<<<NN/8, 256>>>(xp, xph, xpl);
    // 3) qkv = xpn @ W_qkv + b_qkv  [32768,336]x[336,1008]  (MODE0)  <- profiled
    mma_gemm<224,0><<<dim3(5, NN/128), 256, SM_QK>>>(nullptr, xph, xpl,
                                                     wh + OFF_WQKV, wl + OFF_WQKV,
                                                     b_qkv, qkv, NN, E3, EE,
                                                     alpha, dyt_w, dyt_b);
    // 4) scan->conv kernel precompute (needed before conv only)
    prep_kernel<<<EE, 128>>>(A, Bp, Cp, conv_w);
    // 5) sparse attention (kh=1 -> argmax gather) + importance
    attn_kernel<<<NN/4, 128>>>(qkv, att, imp);
    // 6) exact sorted top-819 per batch
    topk_kernel<<<BB, 1024>>>(imp, idx);
    // 7) gather + combined dconv*scan causal convolution -> ys planes
    conv_kernel<<<dim3(EE/56, (KC + 63)/64, BB), 224>>>(att, idx, ysh, ysl);
    // 8) xproc = ys @ W_out + b_out  [6552,336]x[336,512]  (MODE0)
    mma_gemm<192,0><<<dim3(3, (BB*KC + 127)/128), 256, SM_G3>>>(nullptr, ysh, ysl,
                                                                wh + OFF_WOUT, wl + OFF_WOUT,
                                                                b_out, xproc, BB*KC, DIMC, EE,
                                                                alpha, dyt_w, dyt_b);
    // 9) out = residual
    residual_kernel<<<(NN*DIMC/4)/1024, 1024>>>((const float4*)x, (float4*)out);
    // 10) scatter selected rows
    scatter_kernel<<<BB*KC, 128>>>(x, xproc, idx, out);
}

// round 11
// speedup vs baseline: 1.6308x; 1.6308x over previous
#include <cuda_runtime.h>
#include <cuda_fp16.h>
#include <cstdint>

#define DIMC 512
#define EE 336
#define E3 1008
#define NSTATE 16
#define NH 6
#define HDIM 56
#define BB 8
#define LL 4096
#define NN (BB*LL)        // 32768 tokens
#define KC 819
#define DU 64             // truncated scan kernel length
#define DK 67             // combined (scan * dconv) kernel length

// weight plane offsets (half elements) — transposed [n][K] layout
#define OFF_WIN  0
#define OFF_WQKV (512*336)
#define OFF_WOUT (512*336 + 336*1008)
#define WPL_TOTAL (512*336 + 336*1008 + 336*512)

// ---------------- scratch (static device memory; no allocs allowed) ----------
__device__ float  g_xp[(size_t)NN*EE];
__device__ float  g_qkv[(size_t)NN*E3];
__device__ float  g_att[(size_t)NN*EE];
__device__ float  g_imp[NN];
__device__ int    g_idx[BB*KC];
__device__ float  g_xproc[(size_t)BB*KC*DIMC];
__device__ float  g_K[EE*DK];
__device__ __half g_Wh[WPL_TOTAL];          // W^T hi plane [n][K]
__device__ __half g_Wl[WPL_TOTAL];          // W^T lo plane
__device__ __half g_xph[(size_t)NN*EE];     // xpn hi plane [row][k]
__device__ __half g_xpl[(size_t)NN*EE];
__device__ __half g_ysh[(size_t)BB*KC*EE];  // ys hi plane
__device__ __half g_ysl[(size_t)BB*KC*EE];

// ============================ helpers =======================================
__device__ __forceinline__ uint32_t smem_u32(const void* p) {
    uint32_t a;
    asm("{ .reg .u64 t; cvta.to.shared.u64 t, %1; cvt.u32.u64 %0, t; }" : "=r"(a) : "l"(p));
    return a;
}
// fp16 2-term split: v = hi + lo + O(2^-22 v)
__device__ __forceinline__ void f16_split(float v, __half& h, __half& l) {
    h = __float2half_rn(v);
    l = __float2half_rn(v - __half2float(h));
}
__device__ __forceinline__ void mma16(float* c, uint32_t a0, uint32_t a1,
                                      uint32_t a2, uint32_t a3,
                                      uint32_t b0, uint32_t b1) {
    asm volatile("mma.sync.aligned.m16n8k16.row.col.f32.f16.f16.f32 "
        "{%0,%1,%2,%3}, {%4,%5,%6,%7}, {%8,%9}, {%0,%1,%2,%3};"
        : "+f"(c[0]), "+f"(c[1]), "+f"(c[2]), "+f"(c[3])
        : "r"(a0), "r"(a1), "r"(a2), "r"(a3), "r"(b0), "r"(b1));
}
__device__ __forceinline__ void cpa16(uint32_t dst, const void* src, uint32_t sz) {
    asm volatile("cp.async.ca.shared.global [%0], [%1], 16, %2;"
        :: "r"(dst), "l"(src), "r"(sz));
}

// ------- weight split: W[K,N] -> W^T fp16 hi/lo planes [n][k] (tiled) -------
__global__ void wsplit_t_kernel(const float* __restrict__ W0,
                                const float* __restrict__ W1,
                                const float* __restrict__ W2,
                                __half* __restrict__ Wh, __half* __restrict__ Wl)
{
    __shared__ float t[32][33];
    int z = blockIdx.z;
    const float* W = (z == 0) ? W0 : ((z == 1) ? W1 : W2);
    int K = (z == 0) ? 512 : 336;
    int N = (z == 0) ? 336 : ((z == 1) ? 1008 : 512);
    int off = (z == 0) ? OFF_WIN : ((z == 1) ? OFF_WQKV : OFF_WOUT);
    int k0 = blockIdx.x * 32, n0 = blockIdx.y * 32;
    if (k0 >= K || n0 >= N) return;
    int tx = threadIdx.x, ty = threadIdx.y;   // (32, 8)
    #pragma unroll
    for (int i = 0; i < 4; i++) {
        int k = k0 + ty + i * 8, n = n0 + tx;
        if (k < K && n < N) t[ty + i*8][tx] = W[(size_t)k * N + n];
    }
    __syncthreads();
    #pragma unroll
    for (int i = 0; i < 4; i++) {
        int n = n0 + ty + i * 8, k = k0 + tx;
        if (k < K && n < N) {
            __half h, l;
            f16_split(t[tx][ty + i*8], h, l);
            size_t o = (size_t)off + (size_t)n * K + k;
            Wh[o] = h;
            Wl[o] = l;
        }
    }
}

// ============ split-fp16x2 (3-pass) m16n8k16 warp-MMA GEMM ==================
// C[M,N] = op(A)[M,K] @ W[K,N] + bias.  K-chunk 32 (2 k16 steps), 2-stage
// cp.async pipeline.  8 warps (4M x 2N), warp tile 32 x BN/2.
// SMEM planes hold packed half2 words (k-pairs) -> natural m16n8k16 frags.
// MODE 1: A raw fp32 streamed; DyT(tanh)+split transform in-kernel.
// MODE 0: A pre-split hi/lo half planes streamed directly.
template<int BN, int MODE>
__global__ void __launch_bounds__(256, 1) mma_gemm(
    const float* __restrict__ A,
    const __half* __restrict__ Ahg, const __half* __restrict__ Alg,
    const __half* __restrict__ Wh, const __half* __restrict__ Wl,
    const float* __restrict__ bias, float* __restrict__ C,
    int M, int N, int K,
    const float* __restrict__ alpha, const float* __restrict__ dw,
    const float* __restrict__ db)
{
    constexpr int PKA = 20;           // A pitch in words (16 data + 4 pad)
    constexpr int PKB = 20;           // B pitch in words
    constexpr int WN = BN / 2;
    constexpr int NT8 = WN / 8;       // 7 (BN=112) or 8 (BN=128)
    constexpr int PRAW = 36;          // raw fp32 A pitch (MODE1)
    constexpr int AST = (MODE == 0) ? 2 : 1;

    extern __shared__ uint32_t smw[];
    // MODE1: rawA[2][128*PRAW] | AhP[128*PKA] | AlP[...] | Bh[2][BN*PKB] | Bl[2][...]
    // MODE0: AhP[2][128*PKA] | AlP[2][...] | Bh[2][BN*PKB] | Bl[2][...]
    uint32_t* rawA = smw;
    uint32_t* AhP  = smw + ((MODE == 1) ? 2 * 128 * PRAW : 0);
    uint32_t* AlP  = AhP + AST * 128 * PKA;
    uint32_t* BhP  = AlP + AST * 128 * PKA;
    uint32_t* BlP  = BhP + 2 * BN * PKB;

    uint32_t sbase  = smem_u32(smw);
    uint32_t rawA_b = sbase;
    uint32_t AhP_b  = sbase + (uint32_t)(((MODE == 1) ? 2*128*PRAW : 0) * 4);
    uint32_t AlP_b  = AhP_b + (uint32_t)(AST * 128 * PKA * 4);
    uint32_t BhP_b  = AlP_b + (uint32_t)(AST * 128 * PKA * 4);
    uint32_t BlP_b  = BhP_b + (uint32_t)(2 * BN * PKB * 4);

    int tid = threadIdx.x, wid = tid >> 5, lane = tid & 31;
    int wm = (wid & 3) * 32, wn = (wid >> 2) * WN;
    int g4 = lane >> 2, t4 = lane & 3;
    int m0 = blockIdx.y * 128, n0 = blockIdx.x * BN;
    float a0s = (MODE == 1) ? __ldg(alpha) : 0.f;

    float acc[2][NT8][4];
    #pragma unroll
    for (int i = 0; i < 2; i++)
        #pragma unroll
        for (int j = 0; j < NT8; j++)
            #pragma unroll
            for (int t = 0; t < 4; t++) acc[i][j][t] = 0.f;

    int NC = (K + 31) / 32;   // K % 8 == 0 for all call sites

    // ---- async issue of chunk c into stage c&1
    auto issue = [&](int c) {
        int s = c & 1;
        int k0 = c * 32;
        if (MODE == 1) {
            // raw fp32 A: 128 rows x 32 floats = 1024 16B-groups
            #pragma unroll
            for (int it = 0; it < 4; it++) {
                int idx = tid + it * 256;
                int r = idx >> 3, f4 = idx & 7;
                int gm = m0 + r, gk = k0 + f4 * 4;
                bool v = (gm < M) && (gk < K);
                const float* src = v ? (A + (size_t)gm * K + gk) : A;
                cpa16(rawA_b + (uint32_t)((s*128*PRAW + r*PRAW + f4*4) * 4),
                      src, v ? 16u : 0u);
            }
        } else {
            // pre-split half planes: 128 rows x 32 halves = 512 16B-groups/plane
            #pragma unroll
            for (int it = 0; it < 2; it++) {
                int idx = tid + it * 256;
                int r = idx >> 2, f = idx & 3;
                int gm = m0 + r, gk = k0 + f * 8;
                bool v = (gm < M) && (gk < K);
                size_t go = (size_t)gm * K + gk;
                uint32_t so = (uint32_t)((s*128*PKA + r*PKA + f*4) * 4);
                cpa16(AhP_b + so, v ? (const void*)(Ahg + go) : (const void*)Ahg, v ? 16u : 0u);
                cpa16(AlP_b + so, v ? (const void*)(Alg + go) : (const void*)Alg, v ? 16u : 0u);
            }
        }
        // B planes [n][K] half: BN rows x 32 halves = BN*4 16B-groups/plane
        constexpr int BGRP = BN * 4;
        #pragma unroll
        for (int it = 0; it < (BGRP + 255) / 256; it++) {
            int idx = tid + it * 256;
            if (idx < BGRP) {
                int nr = idx >> 2, q = idx & 3;
                int gn = n0 + nr, gk = k0 + q * 8;
                bool v = (gk < K);
                size_t go = (size_t)gn * K + gk;
                uint32_t so = (uint32_t)((s*BN*PKB + nr*PKB + q*4) * 4);
                cpa16(BhP_b + so, v ? (const void*)(Wh + go) : (const void*)Wh, v ? 16u : 0u);
                cpa16(BlP_b + so, v ? (const void*)(Wl + go) : (const void*)Wl, v ? 16u : 0u);
            }
        }
        asm volatile("cp.async.commit_group;" ::: "memory");
    };

    // ---- MODE1 only: raw A -> packed half2 hi/lo planes with DyT fused
    auto transform = [&](int c) {
        int s = c & 1;
        int k0 = c * 32;
        #pragma unroll
        for (int it = 0; it < 4; it++) {
            int idx = tid + it * 256;
            int r = idx >> 3, f4 = idx & 7;
            float4 v = *(const float4*)(rawA + s * 128 * PRAW + r * PRAW + f4 * 4);
            int gk = k0 + f4 * 4;
            float4 w4 = *(const float4*)(dw + gk);
            float4 b4 = *(const float4*)(db + gk);
            v.x = tanhf(a0s * v.x) * w4.x + b4.x;
            v.y = tanhf(a0s * v.y) * w4.y + b4.y;
            v.z = tanhf(a0s * v.z) * w4.z + b4.z;
            v.w = tanhf(a0s * v.w) * w4.w + b4.w;
            __half hx, lx, hy, ly, hz, lz, hw, lw;
            f16_split(v.x, hx, lx);
            f16_split(v.y, hy, ly);
            f16_split(v.z, hz, lz);
            f16_split(v.w, hw, lw);
            __half2 H0 = __halves2half2(hx, hy), H1 = __halves2half2(hz, hw);
            __half2 L0 = __halves2half2(lx, ly), L1 = __halves2half2(lz, lw);
            int wb = r * PKA + f4 * 2;   // word j holds k = 2j, 2j+1
            *(uint2*)(AhP + wb) = make_uint2(*(uint32_t*)&H0, *(uint32_t*)&H1);
            *(uint2*)(AlP + wb) = make_uint2(*(uint32_t*)&L0, *(uint32_t*)&L1);
        }
    };

    // ---- pure LDS+MMA over one 32-wide K chunk (2 k16 steps)
    auto compute = [&](int c) {
        int s = c & 1;
        const uint32_t* Ahb = AhP + ((MODE == 0) ? s * 128 * PKA : 0);
        const uint32_t* Alb = AlP + ((MODE == 0) ? s * 128 * PKA : 0);
        const uint32_t* Bhb = BhP + s * BN * PKB;
        const uint32_t* Blb = BlP + s * BN * PKB;
        #pragma unroll
        for (int kk = 0; kk < 2; kk++) {
            int kw = kk * 8;
            uint32_t ah[2][4], al[2][4];
            #pragma unroll
            for (int mt = 0; mt < 2; mt++) {
                int r0 = (wm + mt * 16 + g4) * PKA + kw + t4;
                ah[mt][0] = Ahb[r0];               // row g4,   k 2t4..2t4+1
                ah[mt][1] = Ahb[r0 + 8 * PKA];     // row g4+8
                ah[mt][2] = Ahb[r0 + 4];           // row g4,   k 2t4+8..+9
                ah[mt][3] = Ahb[r0 + 8 * PKA + 4];
                al[mt][0] = Alb[r0];
                al[mt][1] = Alb[r0 + 8 * PKA];
                al[mt][2] = Alb[r0 + 4];
                al[mt][3] = Alb[r0 + 8 * PKA + 4];
            }
            uint32_t bh[NT8][2], bl[NT8][2];
            #pragma unroll
            for (int nt = 0; nt < NT8; nt++) {
                int nb = (wn + nt * 8 + g4) * PKB + kw + t4;
                bh[nt][0] = Bhb[nb];
                bh[nt][1] = Bhb[nb + 4];
                bl[nt][0] = Blb[nb];
                bl[nt][1] = Blb[nb + 4];
            }
            #pragma unroll
            for (int mt = 0; mt < 2; mt++)
                #pragma unroll
                for (int nt = 0; nt < NT8; nt++) {
                    mma16(acc[mt][nt], ah[mt][0], ah[mt][1], ah[mt][2], ah[mt][3],
                          bh[nt][0], bh[nt][1]);
                    mma16(acc[mt][nt], ah[mt][0], ah[mt][1], ah[mt][2], ah[mt][3],
                          bl[nt][0], bl[nt][1]);
                    mma16(acc[mt][nt], al[mt][0], al[mt][1], al[mt][2], al[mt][3],
                          bh[nt][0], bh[nt][1]);
                }
        }
    };

    issue(0);
    for (int c = 0; c < NC; c++) {
        asm volatile("cp.async.wait_group 0;" ::: "memory");
        __syncthreads();                 // chunk c visible; prev compute done
        if (c + 1 < NC) issue(c + 1);    // overlaps transform/compute of chunk c
        if (MODE == 1) {
            transform(c);
            __syncthreads();
        }
        compute(c);
    }

    // ---- epilogue: registers -> global with bias
    #pragma unroll
    for (int mt = 0; mt < 2; mt++) {
        int gr = m0 + wm + mt * 16 + g4;
        #pragma unroll
        for (int nt = 0; nt < NT8; nt++) {
            int gc = n0 + wn + nt * 8 + t4 * 2;
            float2 bv = *(const float2*)(bias + gc);
            if (gr < M) {
                float2 o = make_float2(acc[mt][nt][0] + bv.x, acc[mt][nt][1] + bv.y);
                *(float2*)(C + (size_t)gr * N + gc) = o;
            }
            if (gr + 8 < M) {
                float2 o = make_float2(acc[mt][nt][2] + bv.x, acc[mt][nt][3] + bv.y);
                *(float2*)(C + (size_t)(gr + 8) * N + gc) = o;
            }
        }
    }
}

// ---------------- prep: combined conv kernel --------------------------------
__global__ void prep_kernel(const float* __restrict__ A, const float* __restrict__ Bp,
                            const float* __restrict__ Cp, const float* __restrict__ cw)
{
    __shared__ float U[DU][NSTATE];
    __shared__ float gk[DU];
    __shared__ float sC[NSTATE];
    int tid = threadIdx.x;
    int e = blockIdx.x;
    if (tid < 32) {
        int i = tid & 15;
        float u = 1.f / (1.f + expf(-Bp[i]));
        for (int d = 0; d < DU; d++) {
            if (tid < 16) U[d][i] = u;
            float nu = 0.f;
            #pragma unroll
            for (int j = 0; j < 16; j++)
                nu += A[i*16 + j] * __shfl_sync(0xFFFFFFFFu, u, j);
            u = nu;
        }
    }
    if (tid < 16) sC[tid] = 1.f / (1.f + expf(-Cp[e*16 + tid]));
    __syncthreads();
    for (int d = tid; d < DU; d += blockDim.x) {
        float s = 0.f;
        #pragma unroll
        for (int i = 0; i < 16; i++) s += sC[i] * U[d][i];
        gk[d] = s;
    }
    __syncthreads();
    for (int dd = tid; dd < DK; dd += blockDim.x) {
        float s = 0.f;
        #pragma unroll
        for (int d1 = 0; d1 < 4; d1++) {
            int d2 = dd - d1;
            if (d2 >= 0 && d2 < DU) s += cw[e*4 + (3 - d1)] * gk[d2];
        }
        g_K[e*DK + dd] = s;
    }
}

// ---------- row L2-normalize -> pre-split fp16 hi/lo planes -----------------
__global__ void norm_kernel(const float* __restrict__ xp,
                            __half* __restrict__ xh, __half* __restrict__ xl)
{
    int lane = threadIdx.x & 31;
    int row = blockIdx.x * 8 + (threadIdx.x >> 5);
    const float* p = xp + (size_t)row * EE;
    float s = 0.f;
    for (int e = lane; e < EE; e += 32) { float v = p[e]; s += v*v; }
    #pragma unroll
    for (int o = 16; o > 0; o >>= 1) s += __shfl_xor_sync(0xFFFFFFFFu, s, o);
    float inv = 1.f / fmaxf(sqrtf(s), 1e-12f);
    for (int e = lane; e < EE; e += 32) {
        float v = p[e] * inv;
        __half h, l;
        f16_split(v, h, l);
        size_t o = (size_t)row * EE + e;
        xh[o] = h;
        xl[o] = l;
    }
}

// ---------------- attention -------------------------------------------------
__global__ void attn_kernel(const float* __restrict__ qkv,
                            float* __restrict__ att, float* __restrict__ imp)
{
    __shared__ float sq[4][E3];
    __shared__ float sc[4][36];
    __shared__ int   gb[4][NH];
    int wid = threadIdx.x >> 5, lane = threadIdx.x & 31;
    int n = blockIdx.x * 4 + wid;
    const float* row = qkv + (size_t)n * E3;
    float* s = sq[wid];
    for (int e = lane; e < E3; e += 32) s[e] = row[e];
    __syncwarp();
    for (int p = lane; p < 36; p += 32) {
        int h = p / 6, g = p - h*6;
        const float* qp = s + h*HDIM;
        const float* kp = s + EE + g*HDIM;
        float d = 0.f;
        #pragma unroll
        for (int t = 0; t < HDIM; t++) d += qp[t] * kp[t];
        sc[wid][p] = d;
    }
    __syncwarp();
    if (lane < NH) {
        float best = sc[wid][lane*6]; int bg = 0;
        #pragma unroll
        for (int g = 1; g < 6; g++) {
            float v = sc[wid][lane*6 + g];
            if (v > best) { best = v; bg = g; }   // strict > : jax tie -> lowest idx
        }
        gb[wid][lane] = bg;
    }
    __syncwarp();
    float acc = 0.f;
    for (int e = lane; e < EE; e += 32) {
        int h = e % NH, d = e / NH;
        float v = s[2*EE + gb[wid][h]*HDIM + d];
        att[(size_t)n*EE + e] = v;
        acc += v*v;
    }
    #pragma unroll
    for (int o = 16; o > 0; o >>= 1) acc += __shfl_xor_sync(0xFFFFFFFFu, acc, o);
    if (lane == 0) imp[n] = sqrtf(acc);
}

// ---------------- top-819 per batch -----------------------------------------
__global__ void topk_kernel(const float* __restrict__ imp, int* __restrict__ idxout)
{
    __shared__ unsigned long long key[LL];
    int b = blockIdx.x;
    for (int i = threadIdx.x; i < LL; i += blockDim.x) {
        unsigned fb = __float_as_uint(imp[b*LL + i]);
        key[i] = ((unsigned long long)(0xFFFFFFFFu - fb) << 32) | (unsigned)i;
    }
    __syncthreads();
    for (int k = 2; k <= LL; k <<= 1)
        for (int j = k >> 1; j > 0; j >>= 1) {
            for (int i = threadIdx.x; i < LL; i += blockDim.x) {
                int ixj = i ^ j;
                if (ixj > i) {
                    bool up = ((i & k) == 0);
                    unsigned long long a = key[i], c = key[ixj];
                    if ((a > c) == up) { key[i] = c; key[ixj] = a; }
                }
            }
            __syncthreads();
        }
    for (int i = threadIdx.x; i < KC; i += blockDim.x)
        idxout[b*KC + i] = (int)(key[i] & 0xFFFFFFFFu);
}

// -------- fused gather + 67-tap causal conv -> fp16 ys planes ---------------
__global__ void __launch_bounds__(224) conv_kernel(const float* __restrict__ att,
                                                   const int* __restrict__ idx,
                                                   __half* __restrict__ ysh,
                                                   __half* __restrict__ ysl)
{
    const int ET = 56, JT = 64, WIN = JT + DK - 1;
    __shared__ float sp[ET][WIN + 1];
    __shared__ float Ks[ET][DK + 1];
    __shared__ int   sidx[WIN];
    int et = blockIdx.x, jt = blockIdx.y, b = blockIdx.z;
    int e0 = et * ET, j0 = jt * JT;
    int tid = threadIdx.x;

    for (int w = tid; w < WIN; w += 224) {
        int j = j0 - (DK - 1) + w;
        sidx[w] = (j >= 0 && j < KC) ? idx[b*KC + j] : -1;
    }
    for (int i = tid; i < ET*DK; i += 224) {
        int ee = i / DK, d = i - ee*DK;
        Ks[ee][d] = g_K[(e0 + ee)*DK + d];
    }
    __syncthreads();
    for (int i = tid; i < WIN*ET; i += 224) {
        int w = i / ET, ee = i - w*ET;
        int pos = sidx[w];
        sp[ee][w] = (pos >= 0) ? att[((size_t)b*LL + pos)*EE + e0 + ee] : 0.f;
    }
    __syncthreads();

    int ee = tid % ET, jg = tid / ET;
    float acc[16];
    #pragma unroll
    for (int t = 0; t < 16; t++) acc[t] = 0.f;
    int wbase = (DK - 1) + jg*16;
    for (int d = 0; d < DK; d++) {
        float kv = Ks[ee][d];
        #pragma unroll
        for (int t = 0; t < 16; t++)
            acc[t] += kv * sp[ee][wbase + t - d];
    }
    #pragma unroll
    for (int t = 0; t < 16; t++) {
        int j = j0 + jg*16 + t;
        if (j < KC) {
            __half h, l;
            f16_split(acc[t], h, l);
            size_t o = ((size_t)b*KC + j)*EE + e0 + ee;
            ysh[o] = h;
            ysl[o] = l;
        }
    }
}

// ---------------- residual copy + scatter -----------------------------------
__global__ void residual_kernel(const float4* __restrict__ x, float4* __restrict__ out)
{
    size_t i = (size_t)blockIdx.x * blockDim.x + threadIdx.x;
    out[i] = x[i];
}

__global__ void scatter_kernel(const float* __restrict__ x, const float* __restrict__ xproc,
                               const int* __restrict__ idx, float* __restrict__ out)
{
    int row = blockIdx.x;
    int b = row / KC, j = row - b*KC;
    int pos = idx[b*KC + j];
    const float* xp = xproc + (size_t)row * DIMC;
    size_t base = ((size_t)b*LL + pos) * DIMC;
    for (int c = threadIdx.x; c < DIMC; c += blockDim.x)
        out[base + c] = x[base + c] + xp[c];
}

// ---------------- launch ----------------------------------------------------
extern "C" void kernel_launch(void* const* d_in, const int* in_sizes, int n_in,
                              void* d_out, int out_size)
{
    const float* x      = (const float*)d_in[0];
    const float* alpha  = (const float*)d_in[1];
    const float* dyt_w  = (const float*)d_in[2];
    const float* dyt_b  = (const float*)d_in[3];
    const float* W_in   = (const float*)d_in[4];
    const float* b_in   = (const float*)d_in[5];
    const float* W_qkv  = (const float*)d_in[6];
    const float* b_qkv  = (const float*)d_in[7];
    const float* conv_w = (const float*)d_in[8];
    const float* A      = (const float*)d_in[9];
    const float* Bp     = (const float*)d_in[10];
    const float* Cp     = (const float*)d_in[11];
    const float* W_out  = (const float*)d_in[12];
    const float* b_out  = (const float*)d_in[13];
    float* out = (float*)d_out;

    float *xp, *qkv, *att, *imp, *xproc;
    __half *wh, *wl, *xph, *xpl, *ysh, *ysl;
    int *idx;
    cudaGetSymbolAddress((void**)&xp,    g_xp);
    cudaGetSymbolAddress((void**)&qkv,   g_qkv);
    cudaGetSymbolAddress((void**)&att,   g_att);
    cudaGetSymbolAddress((void**)&imp,   g_imp);
    cudaGetSymbolAddress((void**)&idx,   g_idx);
    cudaGetSymbolAddress((void**)&xproc, g_xproc);
    cudaGetSymbolAddress((void**)&wh,    g_Wh);
    cudaGetSymbolAddress((void**)&wl,    g_Wl);
    cudaGetSymbolAddress((void**)&xph,   g_xph);
    cudaGetSymbolAddress((void**)&xpl,   g_xpl);
    cudaGetSymbolAddress((void**)&ysh,   g_ysh);
    cudaGetSymbolAddress((void**)&ysl,   g_ysl);

    // smem (bytes):
    // MODE1 BN=112: rawA 2*128*36 + planes 2*128*20 + B 2*2*112*20 = 23296 w = 93184
    // MODE0 BN=112: A 2*2*128*20 + B 2*2*112*20 = 19200 w = 76800
    // MODE0 BN=128: A 10240 + B 2*2*128*20 = 20480 w = 81920
    const int SM_M1  = (2*128*36 + 2*128*20 + 2*2*112*20) * 4;
    const int SM_M0A = (2*2*128*20 + 2*2*112*20) * 4;
    const int SM_M0B = (2*2*128*20 + 2*2*128*20) * 4;
    cudaFuncSetAttribute(mma_gemm<112,1>, cudaFuncAttributeMaxDynamicSharedMemorySize, SM_M1);
    cudaFuncSetAttribute(mma_gemm<112,0>, cudaFuncAttributeMaxDynamicSharedMemorySize, SM_M0A);
    cudaFuncSetAttribute(mma_gemm<128,0>, cudaFuncAttributeMaxDynamicSharedMemorySize, SM_M0B);

    // launch order: qkv GEMM at capture index 3 (matches ncu -s 5 -c 1 slot)
    // 0) all weight planes: transpose + fp16 split
    wsplit_t_kernel<<<dim3(16, 32, 3), dim3(32, 8)>>>(W_in, W_qkv, W_out, wh, wl);
    // 1) xp = dyt(x) @ W_in + b_in   [32768,512]x[512,336]  (MODE1)
    mma_gemm<112,1><<<dim3(3, NN/128), 256, SM_M1>>>(x, nullptr, nullptr,
                                                     wh + OFF_WIN, wl + OFF_WIN,
                                                     b_in, xp, NN, EE, DIMC,
                                                     alpha, dyt_w, dyt_b);
    // 2) row-normalize -> pre-split xpn planes
    norm_kernel<<<NN/8, 256>>>(xp, xph, xpl);
    // 3) qkv = xpn @ W_qkv + b_qkv  [32768,336]x[336,1008]  (MODE0)  <- profiled
    mma_gemm<112,0><<<dim3(9, NN/128), 256, SM_M0A>>>(nullptr, xph, xpl,
                                                      wh + OFF_WQKV, wl + OFF_WQKV,
                                                      b_qkv, qkv, NN, E3, EE,
                                                      alpha, dyt_w, dyt_b);
    // 4) scan->conv kernel precompute
    prep_kernel<<<EE, 128>>>(A, Bp, Cp, conv_w);
    // 5) sparse attention (kh=1 -> argmax gather) + importance
    attn_kernel<<<NN/4, 128>>>(qkv, att, imp);
    // 6) exact sorted top-819 per batch
    topk_kernel<<<BB, 1024>>>(imp, idx);
    // 7) gather + combined dconv*scan causal convolution -> ys planes
    conv_kernel<<<dim3(EE/56, (KC + 63)/64, BB), 224>>>(att, idx, ysh, ysl);
    // 8) xproc = ys @ W_out + b_out  [6552,336]x[336,512]  (MODE0)
    mma_gemm<128,0><<<dim3(4, (BB*KC + 127)/128), 256, SM_M0B>>>(nullptr, ysh, ysl,
                                                                 wh + OFF_WOUT, wl + OFF_WOUT,
                                                                 b_out, xproc, BB*KC, DIMC, EE,
                                                                 alpha, dyt_w, dyt_b);
    // 9) out = residual
    residual_kernel<<<(NN*DIMC/4)/1024, 1024>>>((const float4*)x, (float4*)out);
    // 10) scatter selected rows
    scatter_kernel<<<BB*KC, 128>>>(x, xproc, idx, out);
}

// round 12
// speedup vs baseline: 1.8421x; 1.1296x over previous
#include <cuda_runtime.h>
#include <cuda_fp16.h>
#include <cstdint>

#define DIMC 512
#define EE 336
#define E3 1008
#define NSTATE 16
#define NH 6
#define HDIM 56
#define BB 8
#define LL 4096
#define NN (BB*LL)        // 32768 tokens
#define KC 819
#define DU 64             // truncated scan kernel length
#define DK 67             // combined (scan * dconv) kernel length

// weight plane offsets (half elements) — transposed [n][K] layout
#define OFF_WIN  0
#define OFF_WQKV (512*336)
#define OFF_WOUT (512*336 + 336*1008)
#define WPL_TOTAL (512*336 + 336*1008 + 336*512)

// ---------------- scratch (static device memory; no allocs allowed) ----------
__device__ float  g_xp[(size_t)NN*EE];
__device__ float  g_qkv[(size_t)NN*E3];
__device__ float  g_att[(size_t)NN*EE];
__device__ float  g_imp[NN];
__device__ int    g_idx[BB*KC];
__device__ float  g_xproc[(size_t)BB*KC*DIMC];
__device__ float  g_K[EE*DK];
__device__ __half g_Wh[WPL_TOTAL];          // W^T hi plane [n][K]
__device__ __half g_Wl[WPL_TOTAL];          // W^T lo plane
__device__ __half g_xph[(size_t)NN*EE];     // xpn hi plane [row][k]
__device__ __half g_xpl[(size_t)NN*EE];
__device__ __half g_ysh[(size_t)BB*KC*EE];  // ys hi plane
__device__ __half g_ysl[(size_t)BB*KC*EE];

// ============================ helpers =======================================
__device__ __forceinline__ uint32_t smem_u32(const void* p) {
    uint32_t a;
    asm("{ .reg .u64 t; cvta.to.shared.u64 t, %1; cvt.u32.u64 %0, t; }" : "=r"(a) : "l"(p));
    return a;
}
// fp16 2-term split: v = hi + lo + O(2^-22 v)
__device__ __forceinline__ void f16_split(float v, __half& h, __half& l) {
    h = __float2half_rn(v);
    l = __float2half_rn(v - __half2float(h));
}
__device__ __forceinline__ void mma16(float* c, uint32_t a0, uint32_t a1,
                                      uint32_t a2, uint32_t a3,
                                      uint32_t b0, uint32_t b1) {
    asm volatile("mma.sync.aligned.m16n8k16.row.col.f32.f16.f16.f32 "
        "{%0,%1,%2,%3}, {%4,%5,%6,%7}, {%8,%9}, {%0,%1,%2,%3};"
        : "+f"(c[0]), "+f"(c[1]), "+f"(c[2]), "+f"(c[3])
        : "r"(a0), "r"(a1), "r"(a2), "r"(a3), "r"(b0), "r"(b1));
}
__device__ __forceinline__ void cpa16(uint32_t dst, const void* src, uint32_t sz) {
    asm volatile("cp.async.ca.shared.global [%0], [%1], 16, %2;"
        :: "r"(dst), "l"(src), "r"(sz));
}

// ------- weight split: W[K,N] -> W^T fp16 hi/lo planes [n][k] (tiled) -------
__global__ void wsplit_t_kernel(const float* __restrict__ W0,
                                const float* __restrict__ W1,
                                const float* __restrict__ W2,
                                __half* __restrict__ Wh, __half* __restrict__ Wl)
{
    __shared__ float t[32][33];
    int z = blockIdx.z;
    const float* W = (z == 0) ? W0 : ((z == 1) ? W1 : W2);
    int K = (z == 0) ? 512 : 336;
    int N = (z == 0) ? 336 : ((z == 1) ? 1008 : 512);
    int off = (z == 0) ? OFF_WIN : ((z == 1) ? OFF_WQKV : OFF_WOUT);
    int k0 = blockIdx.x * 32, n0 = blockIdx.y * 32;
    if (k0 >= K || n0 >= N) return;
    int tx = threadIdx.x, ty = threadIdx.y;   // (32, 8)
    #pragma unroll
    for (int i = 0; i < 4; i++) {
        int k = k0 + ty + i * 8, n = n0 + tx;
        if (k < K && n < N) t[ty + i*8][tx] = W[(size_t)k * N + n];
    }
    __syncthreads();
    #pragma unroll
    for (int i = 0; i < 4; i++) {
        int n = n0 + ty + i * 8, k = k0 + tx;
        if (k < K && n < N) {
            __half h, l;
            f16_split(t[tx][ty + i*8], h, l);
            size_t o = (size_t)off + (size_t)n * K + k;
            Wh[o] = h;
            Wl[o] = l;
        }
    }
}

// ============ split-fp16x2 (3-pass) m16n8k16 warp-MMA GEMM ==================
// C[M,N] = op(A)[M,K] @ W[K,N] + bias.  K-chunk 32 (2 k16 steps), 2-stage
// cp.async pipeline.  8 warps (4M x 2N), warp tile 32 x BN/2.
// NOW 2 CTAs/SM (the single change vs R11) — tests issue-coverage theory.
// MODE 1: A raw fp32 streamed; DyT(tanh)+split transform in-kernel.
// MODE 0: A pre-split hi/lo half planes streamed directly.
template<int BN, int MODE>
__global__ void __launch_bounds__(256, 2) mma_gemm(
    const float* __restrict__ A,
    const __half* __restrict__ Ahg, const __half* __restrict__ Alg,
    const __half* __restrict__ Wh, const __half* __restrict__ Wl,
    const float* __restrict__ bias, float* __restrict__ C,
    int M, int N, int K,
    const float* __restrict__ alpha, const float* __restrict__ dw,
    const float* __restrict__ db)
{
    constexpr int PKA = 20;           // A pitch in words (16 data + 4 pad)
    constexpr int PKB = 20;           // B pitch in words
    constexpr int WN = BN / 2;
    constexpr int NT8 = WN / 8;       // 7 (BN=112) or 8 (BN=128)
    constexpr int PRAW = 36;          // raw fp32 A pitch (MODE1)
    constexpr int AST = (MODE == 0) ? 2 : 1;

    extern __shared__ uint32_t smw[];
    uint32_t* rawA = smw;
    uint32_t* AhP  = smw + ((MODE == 1) ? 2 * 128 * PRAW : 0);
    uint32_t* AlP  = AhP + AST * 128 * PKA;
    uint32_t* BhP  = AlP + AST * 128 * PKA;
    uint32_t* BlP  = BhP + 2 * BN * PKB;

    uint32_t sbase  = smem_u32(smw);
    uint32_t rawA_b = sbase;
    uint32_t AhP_b  = sbase + (uint32_t)(((MODE == 1) ? 2*128*PRAW : 0) * 4);
    uint32_t AlP_b  = AhP_b + (uint32_t)(AST * 128 * PKA * 4);
    uint32_t BhP_b  = AlP_b + (uint32_t)(AST * 128 * PKA * 4);
    uint32_t BlP_b  = BhP_b + (uint32_t)(2 * BN * PKB * 4);

    int tid = threadIdx.x, wid = tid >> 5, lane = tid & 31;
    int wm = (wid & 3) * 32, wn = (wid >> 2) * WN;
    int g4 = lane >> 2, t4 = lane & 3;
    int m0 = blockIdx.y * 128, n0 = blockIdx.x * BN;
    float a0s = (MODE == 1) ? __ldg(alpha) : 0.f;

    float acc[2][NT8][4];
    #pragma unroll
    for (int i = 0; i < 2; i++)
        #pragma unroll
        for (int j = 0; j < NT8; j++)
            #pragma unroll
            for (int t = 0; t < 4; t++) acc[i][j][t] = 0.f;

    int NC = (K + 31) / 32;

    // ---- async issue of chunk c into stage c&1
    auto issue = [&](int c) {
        int s = c & 1;
        int k0 = c * 32;
        if (MODE == 1) {
            #pragma unroll
            for (int it = 0; it < 4; it++) {
                int idx = tid + it * 256;
                int r = idx >> 3, f4 = idx & 7;
                int gm = m0 + r, gk = k0 + f4 * 4;
                bool v = (gm < M) && (gk < K);
                const float* src = v ? (A + (size_t)gm * K + gk) : A;
                cpa16(rawA_b + (uint32_t)((s*128*PRAW + r*PRAW + f4*4) * 4),
                      src, v ? 16u : 0u);
            }
        } else {
            #pragma unroll
            for (int it = 0; it < 2; it++) {
                int idx = tid + it * 256;
                int r = idx >> 2, f = idx & 3;
                int gm = m0 + r, gk = k0 + f * 8;
                bool v = (gm < M) && (gk < K);
                size_t go = (size_t)gm * K + gk;
                uint32_t so = (uint32_t)((s*128*PKA + r*PKA + f*4) * 4);
                cpa16(AhP_b + so, v ? (const void*)(Ahg + go) : (const void*)Ahg, v ? 16u : 0u);
                cpa16(AlP_b + so, v ? (const void*)(Alg + go) : (const void*)Alg, v ? 16u : 0u);
            }
        }
        constexpr int BGRP = BN * 4;
        #pragma unroll
        for (int it = 0; it < (BGRP + 255) / 256; it++) {
            int idx = tid + it * 256;
            if (idx < BGRP) {
                int nr = idx >> 2, q = idx & 3;
                int gn = n0 + nr, gk = k0 + q * 8;
                bool v = (gk < K);
                size_t go = (size_t)gn * K + gk;
                uint32_t so = (uint32_t)((s*BN*PKB + nr*PKB + q*4) * 4);
                cpa16(BhP_b + so, v ? (const void*)(Wh + go) : (const void*)Wh, v ? 16u : 0u);
                cpa16(BlP_b + so, v ? (const void*)(Wl + go) : (const void*)Wl, v ? 16u : 0u);
            }
        }
        asm volatile("cp.async.commit_group;" ::: "memory");
    };

    // ---- MODE1 only: raw A -> packed half2 hi/lo planes with DyT fused
    auto transform = [&](int c) {
        int s = c & 1;
        int k0 = c * 32;
        #pragma unroll
        for (int it = 0; it < 4; it++) {
            int idx = tid + it * 256;
            int r = idx >> 3, f4 = idx & 7;
            float4 v = *(const float4*)(rawA + s * 128 * PRAW + r * PRAW + f4 * 4);
            int gk = k0 + f4 * 4;
            float4 w4 = *(const float4*)(dw + gk);
            float4 b4 = *(const float4*)(db + gk);
            v.x = tanhf(a0s * v.x) * w4.x + b4.x;
            v.y = tanhf(a0s * v.y) * w4.y + b4.y;
            v.z = tanhf(a0s * v.z) * w4.z + b4.z;
            v.w = tanhf(a0s * v.w) * w4.w + b4.w;
            __half hx, lx, hy, ly, hz, lz, hw, lw;
            f16_split(v.x, hx, lx);
            f16_split(v.y, hy, ly);
            f16_split(v.z, hz, lz);
            f16_split(v.w, hw, lw);
            __half2 H0 = __halves2half2(hx, hy), H1 = __halves2half2(hz, hw);
            __half2 L0 = __halves2half2(lx, ly), L1 = __halves2half2(lz, lw);
            int wb = r * PKA + f4 * 2;   // word j holds k = 2j, 2j+1
            *(uint2*)(AhP + wb) = make_uint2(*(uint32_t*)&H0, *(uint32_t*)&H1);
            *(uint2*)(AlP + wb) = make_uint2(*(uint32_t*)&L0, *(uint32_t*)&L1);
        }
    };

    // ---- pure LDS+MMA over one 32-wide K chunk (2 k16 steps)
    auto compute = [&](int c) {
        int s = c & 1;
        const uint32_t* Ahb = AhP + ((MODE == 0) ? s * 128 * PKA : 0);
        const uint32_t* Alb = AlP + ((MODE == 0) ? s * 128 * PKA : 0);
        const uint32_t* Bhb = BhP + s * BN * PKB;
        const uint32_t* Blb = BlP + s * BN * PKB;
        #pragma unroll
        for (int kk = 0; kk < 2; kk++) {
            int kw = kk * 8;
            uint32_t ah[2][4], al[2][4];
            #pragma unroll
            for (int mt = 0; mt < 2; mt++) {
                int r0 = (wm + mt * 16 + g4) * PKA + kw + t4;
                ah[mt][0] = Ahb[r0];
                ah[mt][1] = Ahb[r0 + 8 * PKA];
                ah[mt][2] = Ahb[r0 + 4];
                ah[mt][3] = Ahb[r0 + 8 * PKA + 4];
                al[mt][0] = Alb[r0];
                al[mt][1] = Alb[r0 + 8 * PKA];
                al[mt][2] = Alb[r0 + 4];
                al[mt][3] = Alb[r0 + 8 * PKA + 4];
            }
            uint32_t bh[NT8][2], bl[NT8][2];
            #pragma unroll
            for (int nt = 0; nt < NT8; nt++) {
                int nb = (wn + nt * 8 + g4) * PKB + kw + t4;
                bh[nt][0] = Bhb[nb];
                bh[nt][1] = Bhb[nb + 4];
                bl[nt][0] = Blb[nb];
                bl[nt][1] = Blb[nb + 4];
            }
            #pragma unroll
            for (int mt = 0; mt < 2; mt++)
                #pragma unroll
                for (int nt = 0; nt < NT8; nt++) {
                    mma16(acc[mt][nt], ah[mt][0], ah[mt][1], ah[mt][2], ah[mt][3],
                          bh[nt][0], bh[nt][1]);
                    mma16(acc[mt][nt], ah[mt][0], ah[mt][1], ah[mt][2], ah[mt][3],
                          bl[nt][0], bl[nt][1]);
                    mma16(acc[mt][nt], al[mt][0], al[mt][1], al[mt][2], al[mt][3],
                          bh[nt][0], bh[nt][1]);
                }
        }
    };

    issue(0);
    for (int c = 0; c < NC; c++) {
        asm volatile("cp.async.wait_group 0;" ::: "memory");
        __syncthreads();                 // chunk c visible; prev compute done
        if (c + 1 < NC) issue(c + 1);    // overlaps transform/compute of chunk c
        if (MODE == 1) {
            transform(c);
            __syncthreads();
        }
        compute(c);
    }

    // ---- epilogue: registers -> global with bias
    #pragma unroll
    for (int mt = 0; mt < 2; mt++) {
        int gr = m0 + wm + mt * 16 + g4;
        #pragma unroll
        for (int nt = 0; nt < NT8; nt++) {
            int gc = n0 + wn + nt * 8 + t4 * 2;
            float2 bv = *(const float2*)(bias + gc);
            if (gr < M) {
                float2 o = make_float2(acc[mt][nt][0] + bv.x, acc[mt][nt][1] + bv.y);
                *(float2*)(C + (size_t)gr * N + gc) = o;
            }
            if (gr + 8 < M) {
                float2 o = make_float2(acc[mt][nt][2] + bv.x, acc[mt][nt][3] + bv.y);
                *(float2*)(C + (size_t)(gr + 8) * N + gc) = o;
            }
        }
    }
}

// ---------------- prep: combined conv kernel --------------------------------
__global__ void prep_kernel(const float* __restrict__ A, const float* __restrict__ Bp,
                            const float* __restrict__ Cp, const float* __restrict__ cw)
{
    __shared__ float U[DU][NSTATE];
    __shared__ float gk[DU];
    __shared__ float sC[NSTATE];
    int tid = threadIdx.x;
    int e = blockIdx.x;
    if (tid < 32) {
        int i = tid & 15;
        float u = 1.f / (1.f + expf(-Bp[i]));
        for (int d = 0; d < DU; d++) {
            if (tid < 16) U[d][i] = u;
            float nu = 0.f;
            #pragma unroll
            for (int j = 0; j < 16; j++)
                nu += A[i*16 + j] * __shfl_sync(0xFFFFFFFFu, u, j);
            u = nu;
        }
    }
    if (tid < 16) sC[tid] = 1.f / (1.f + expf(-Cp[e*16 + tid]));
    __syncthreads();
    for (int d = tid; d < DU; d += blockDim.x) {
        float s = 0.f;
        #pragma unroll
        for (int i = 0; i < 16; i++) s += sC[i] * U[d][i];
        gk[d] = s;
    }
    __syncthreads();
    for (int dd = tid; dd < DK; dd += blockDim.x) {
        float s = 0.f;
        #pragma unroll
        for (int d1 = 0; d1 < 4; d1++) {
            int d2 = dd - d1;
            if (d2 >= 0 && d2 < DU) s += cw[e*4 + (3 - d1)] * gk[d2];
        }
        g_K[e*DK + dd] = s;
    }
}

// ---------- row L2-normalize -> pre-split fp16 hi/lo planes -----------------
__global__ void norm_kernel(const float* __restrict__ xp,
                            __half* __restrict__ xh, __half* __restrict__ xl)
{
    int lane = threadIdx.x & 31;
    int row = blockIdx.x * 8 + (threadIdx.x >> 5);
    const float* p = xp + (size_t)row * EE;
    float s = 0.f;
    for (int e = lane; e < EE; e += 32) { float v = p[e]; s += v*v; }
    #pragma unroll
    for (int o = 16; o > 0; o >>= 1) s += __shfl_xor_sync(0xFFFFFFFFu, s, o);
    float inv = 1.f / fmaxf(sqrtf(s), 1e-12f);
    for (int e = lane; e < EE; e += 32) {
        float v = p[e] * inv;
        __half h, l;
        f16_split(v, h, l);
        size_t o = (size_t)row * EE + e;
        xh[o] = h;
        xl[o] = l;
    }
}

// ---------------- attention -------------------------------------------------
__global__ void attn_kernel(const float* __restrict__ qkv,
                            float* __restrict__ att, float* __restrict__ imp)
{
    __shared__ float sq[4][E3];
    __shared__ float sc[4][36];
    __shared__ int   gb[4][NH];
    int wid = threadIdx.x >> 5, lane = threadIdx.x & 31;
    int n = blockIdx.x * 4 + wid;
    const float* row = qkv + (size_t)n * E3;
    float* s = sq[wid];
    for (int e = lane; e < E3; e += 32) s[e] = row[e];
    __syncwarp();
    for (int p = lane; p < 36; p += 32) {
        int h = p / 6, g = p - h*6;
        const float* qp = s + h*HDIM;
        const float* kp = s + EE + g*HDIM;
        float d = 0.f;
        #pragma unroll
        for (int t = 0; t < HDIM; t++) d += qp[t] * kp[t];
        sc[wid][p] = d;
    }
    __syncwarp();
    if (lane < NH) {
        float best = sc[wid][lane*6]; int bg = 0;
        #pragma unroll
        for (int g = 1; g < 6; g++) {
            float v = sc[wid][lane*6 + g];
            if (v > best) { best = v; bg = g; }   // strict > : jax tie -> lowest idx
        }
        gb[wid][lane] = bg;
    }
    __syncwarp();
    float acc = 0.f;
    for (int e = lane; e < EE; e += 32) {
        int h = e % NH, d = e / NH;
        float v = s[2*EE + gb[wid][h]*HDIM + d];
        att[(size_t)n*EE + e] = v;
        acc += v*v;
    }
    #pragma unroll
    for (int o = 16; o > 0; o >>= 1) acc += __shfl_xor_sync(0xFFFFFFFFu, acc, o);
    if (lane == 0) imp[n] = sqrtf(acc);
}

// ---------------- top-819 per batch -----------------------------------------
__global__ void topk_kernel(const float* __restrict__ imp, int* __restrict__ idxout)
{
    __shared__ unsigned long long key[LL];
    int b = blockIdx.x;
    for (int i = threadIdx.x; i < LL; i += blockDim.x) {
        unsigned fb = __float_as_uint(imp[b*LL + i]);
        key[i] = ((unsigned long long)(0xFFFFFFFFu - fb) << 32) | (unsigned)i;
    }
    __syncthreads();
    for (int k = 2; k <= LL; k <<= 1)
        for (int j = k >> 1; j > 0; j >>= 1) {
            for (int i = threadIdx.x; i < LL; i += blockDim.x) {
                int ixj = i ^ j;
                if (ixj > i) {
                    bool up = ((i & k) == 0);
                    unsigned long long a = key[i], c = key[ixj];
                    if ((a > c) == up) { key[i] = c; key[ixj] = a; }
                }
            }
            __syncthreads();
        }
    for (int i = threadIdx.x; i < KC; i += blockDim.x)
        idxout[b*KC + i] = (int)(key[i] & 0xFFFFFFFFu);
}

// -------- fused gather + 67-tap causal conv -> fp16 ys planes ---------------
__global__ void __launch_bounds__(224) conv_kernel(const float* __restrict__ att,
                                                   const int* __restrict__ idx,
                                                   __half* __restrict__ ysh,
                                                   __half* __restrict__ ysl)
{
    const int ET = 56, JT = 64, WIN = JT + DK - 1;
    __shared__ float sp[ET][WIN + 1];
    __shared__ float Ks[ET][DK + 1];
    __shared__ int   sidx[WIN];
    int et = blockIdx.x, jt = blockIdx.y, b = blockIdx.z;
    int e0 = et * ET, j0 = jt * JT;
    int tid = threadIdx.x;

    for (int w = tid; w < WIN; w += 224) {
        int j = j0 - (DK - 1) + w;
        sidx[w] = (j >= 0 && j < KC) ? idx[b*KC + j] : -1;
    }
    for (int i = tid; i < ET*DK; i += 224) {
        int ee = i / DK, d = i - ee*DK;
        Ks[ee][d] = g_K[(e0 + ee)*DK + d];
    }
    __syncthreads();
    for (int i = tid; i < WIN*ET; i += 224) {
        int w = i / ET, ee = i - w*ET;
        int pos = sidx[w];
        sp[ee][w] = (pos >= 0) ? att[((size_t)b*LL + pos)*EE + e0 + ee] : 0.f;
    }
    __syncthreads();

    int ee = tid % ET, jg = tid / ET;
    float acc[16];
    #pragma unroll
    for (int t = 0; t < 16; t++) acc[t] = 0.f;
    int wbase = (DK - 1) + jg*16;
    for (int d = 0; d < DK; d++) {
        float kv = Ks[ee][d];
        #pragma unroll
        for (int t = 0; t < 16; t++)
            acc[t] += kv * sp[ee][wbase + t - d];
    }
    #pragma unroll
    for (int t = 0; t < 16; t++) {
        int j = j0 + jg*16 + t;
        if (j < KC) {
            __half h, l;
            f16_split(acc[t], h, l);
            size_t o = ((size_t)b*KC + j)*EE + e0 + ee;
            ysh[o] = h;
            ysl[o] = l;
        }
    }
}

// ---------------- residual copy + scatter -----------------------------------
__global__ void residual_kernel(const float4* __restrict__ x, float4* __restrict__ out)
{
    size_t i = (size_t)blockIdx.x * blockDim.x + threadIdx.x;
    out[i] = x[i];
}

__global__ void scatter_kernel(const float* __restrict__ x, const float* __restrict__ xproc,
                               const int* __restrict__ idx, float* __restrict__ out)
{
    int row = blockIdx.x;
    int b = row / KC, j = row - b*KC;
    int pos = idx[b*KC + j];
    const float* xp = xproc + (size_t)row * DIMC;
    size_t base = ((size_t)b*LL + pos) * DIMC;
    for (int c = threadIdx.x; c < DIMC; c += blockDim.x)
        out[base + c] = x[base + c] + xp[c];
}

// ---------------- launch ----------------------------------------------------
extern "C" void kernel_launch(void* const* d_in, const int* in_sizes, int n_in,
                              void* d_out, int out_size)
{
    const float* x      = (const float*)d_in[0];
    const float* alpha  = (const float*)d_in[1];
    const float* dyt_w  = (const float*)d_in[2];
    const float* dyt_b  = (const float*)d_in[3];
    const float* W_in   = (const float*)d_in[4];
    const float* b_in   = (const float*)d_in[5];
    const float* W_qkv  = (const float*)d_in[6];
    const float* b_qkv  = (const float*)d_in[7];
    const float* conv_w = (const float*)d_in[8];
    const float* A      = (const float*)d_in[9];
    const float* Bp     = (const float*)d_in[10];
    const float* Cp     = (const float*)d_in[11];
    const float* W_out  = (const float*)d_in[12];
    const float* b_out  = (const float*)d_in[13];
    float* out = (float*)d_out;

    float *xp, *qkv, *att, *imp, *xproc;
    __half *wh, *wl, *xph, *xpl, *ysh, *ysl;
    int *idx;
    cudaGetSymbolAddress((void**)&xp,    g_xp);
    cudaGetSymbolAddress((void**)&qkv,   g_qkv);
    cudaGetSymbolAddress((void**)&att,   g_att);
    cudaGetSymbolAddress((void**)&imp,   g_imp);
    cudaGetSymbolAddress((void**)&idx,   g_idx);
    cudaGetSymbolAddress((void**)&xproc, g_xproc);
    cudaGetSymbolAddress((void**)&wh,    g_Wh);
    cudaGetSymbolAddress((void**)&wl,    g_Wl);
    cudaGetSymbolAddress((void**)&xph,   g_xph);
    cudaGetSymbolAddress((void**)&xpl,   g_xpl);
    cudaGetSymbolAddress((void**)&ysh,   g_ysh);
    cudaGetSymbolAddress((void**)&ysl,   g_ysl);

    // smem (bytes), all fit 2 CTAs/SM (<=114 KB each):
    // MODE1 BN=112: 93184;  MODE0 BN=112: 76800;  MODE0 BN=128: 81920
    const int SM_M1  = (2*128*36 + 2*128*20 + 2*2*112*20) * 4;
    const int SM_M0A = (2*2*128*20 + 2*2*112*20) * 4;
    const int SM_M0B = (2*2*128*20 + 2*2*128*20) * 4;
    cudaFuncSetAttribute(mma_gemm<112,1>, cudaFuncAttributeMaxDynamicSharedMemorySize, SM_M1);
    cudaFuncSetAttribute(mma_gemm<112,0>, cudaFuncAttributeMaxDynamicSharedMemorySize, SM_M0A);
    cudaFuncSetAttribute(mma_gemm<128,0>, cudaFuncAttributeMaxDynamicSharedMemorySize, SM_M0B);

    // launch order: qkv GEMM at capture index 3 (matches ncu -s 5 -c 1 slot)
    // 0) all weight planes: transpose + fp16 split
    wsplit_t_kernel<<<dim3(16, 32, 3), dim3(32, 8)>>>(W_in, W_qkv, W_out, wh, wl);
    // 1) xp = dyt(x) @ W_in + b_in   [32768,512]x[512,336]  (MODE1)
    mma_gemm<112,1><<<dim3(3, NN/128), 256, SM_M1>>>(x, nullptr, nullptr,
                                                     wh + OFF_WIN, wl + OFF_WIN,
                                                     b_in, xp, NN, EE, DIMC,
                                                     alpha, dyt_w, dyt_b);
    // 2) row-normalize -> pre-split xpn planes
    norm_kernel<<<NN/8, 256>>>(xp, xph, xpl);
    // 3) qkv = xpn @ W_qkv + b_qkv  [32768,336]x[336,1008]  (MODE0)  <- profiled
    mma_gemm<112,0><<<dim3(9, NN/128), 256, SM_M0A>>>(nullptr, xph, xpl,
                                                      wh + OFF_WQKV, wl + OFF_WQKV,
                                                      b_qkv, qkv, NN, E3, EE,
                                                      alpha, dyt_w, dyt_b);
    // 4) scan->conv kernel precompute
    prep_kernel<<<EE, 128>>>(A, Bp, Cp, conv_w);
    // 5) sparse attention (kh=1 -> argmax gather) + importance
    attn_kernel<<<NN/4, 128>>>(qkv, att, imp);
    // 6) exact sorted top-819 per batch
    topk_kernel<<<BB, 1024>>>(imp, idx);
    // 7) gather + combined dconv*scan causal convolution -> ys planes
    conv_kernel<<<dim3(EE/56, (KC + 63)/64, BB), 224>>>(att, idx, ysh, ysl);
    // 8) xproc = ys @ W_out + b_out  [6552,336]x[336,512]  (MODE0)
    mma_gemm<128,0><<<dim3(4, (BB*KC + 127)/128), 256, SM_M0B>>>(nullptr, ysh, ysl,
                                                                 wh + OFF_WOUT, wl + OFF_WOUT,
                                                                 b_out, xproc, BB*KC, DIMC, EE,
                                                                 alpha, dyt_w, dyt_b);
    // 9) out = residual
    residual_kernel<<<(NN*DIMC/4)/1024, 1024>>>((const float4*)x, (float4*)out);
    // 10) scatter selected rows
    scatter_kernel<<<BB*KC, 128>>>(x, xproc, idx, out);
}

// round 13
// speedup vs baseline: 1.9821x; 1.0760x over previous
#include <cuda_runtime.h>
#include <cuda_fp16.h>
#include <cstdint>

#define DIMC 512
#define EE 336
#define E3 1008
#define NSTATE 16
#define NH 6
#define HDIM 56
#define BB 8
#define LL 4096
#define NN (BB*LL)        // 32768 tokens
#define KC 819
#define DU 64             // truncated scan kernel length
#define DK 67             // combined (scan * dconv) kernel length

// weight plane offsets (half elements) — transposed [n][K] layout
#define OFF_WIN  0
#define OFF_WQKV (512*336)
#define OFF_WOUT (512*336 + 336*1008)
#define WPL_TOTAL (512*336 + 336*1008 + 336*512)

// ---------------- scratch (static device memory; no allocs allowed) ----------
__device__ float  g_xp[(size_t)NN*EE];
__device__ float  g_qkv[(size_t)NN*E3];
__device__ float  g_att[(size_t)NN*EE];
__device__ float  g_imp[NN];
__device__ int    g_idx[BB*KC];
__device__ int    g_inv[NN];                // row -> global xproc row (or -1)
__device__ float  g_xproc[(size_t)BB*KC*DIMC];
__device__ float  g_K[EE*DK];
__device__ __half g_Wh[WPL_TOTAL];          // W^T hi plane [n][K]
__device__ __half g_Wl[WPL_TOTAL];          // W^T lo plane
__device__ __half g_xph[(size_t)NN*EE];     // xpn hi plane [row][k]
__device__ __half g_xpl[(size_t)NN*EE];
__device__ __half g_ysh[(size_t)BB*KC*EE];  // ys hi plane
__device__ __half g_ysl[(size_t)BB*KC*EE];

// ============================ helpers =======================================
__device__ __forceinline__ uint32_t smem_u32(const void* p) {
    uint32_t a;
    asm("{ .reg .u64 t; cvta.to.shared.u64 t, %1; cvt.u32.u64 %0, t; }" : "=r"(a) : "l"(p));
    return a;
}
// fp16 2-term split: v = hi + lo + O(2^-22 v)
__device__ __forceinline__ void f16_split(float v, __half& h, __half& l) {
    h = __float2half_rn(v);
    l = __float2half_rn(v - __half2float(h));
}
__device__ __forceinline__ void mma16(float* c, uint32_t a0, uint32_t a1,
                                      uint32_t a2, uint32_t a3,
                                      uint32_t b0, uint32_t b1) {
    asm volatile("mma.sync.aligned.m16n8k16.row.col.f32.f16.f16.f32 "
        "{%0,%1,%2,%3}, {%4,%5,%6,%7}, {%8,%9}, {%0,%1,%2,%3};"
        : "+f"(c[0]), "+f"(c[1]), "+f"(c[2]), "+f"(c[3])
        : "r"(a0), "r"(a1), "r"(a2), "r"(a3), "r"(b0), "r"(b1));
}
__device__ __forceinline__ void cpa16(uint32_t dst, const void* src, uint32_t sz) {
    asm volatile("cp.async.ca.shared.global [%0], [%1], 16, %2;"
        :: "r"(dst), "l"(src), "r"(sz));
}

// ------- weight split: W[K,N] -> W^T fp16 hi/lo planes [n][k] (tiled) -------
__global__ void wsplit_t_kernel(const float* __restrict__ W0,
                                const float* __restrict__ W1,
                                const float* __restrict__ W2,
                                __half* __restrict__ Wh, __half* __restrict__ Wl)
{
    __shared__ float t[32][33];
    int z = blockIdx.z;
    const float* W = (z == 0) ? W0 : ((z == 1) ? W1 : W2);
    int K = (z == 0) ? 512 : 336;
    int N = (z == 0) ? 336 : ((z == 1) ? 1008 : 512);
    int off = (z == 0) ? OFF_WIN : ((z == 1) ? OFF_WQKV : OFF_WOUT);
    int k0 = blockIdx.x * 32, n0 = blockIdx.y * 32;
    if (k0 >= K || n0 >= N) return;
    int tx = threadIdx.x, ty = threadIdx.y;   // (32, 8)
    #pragma unroll
    for (int i = 0; i < 4; i++) {
        int k = k0 + ty + i * 8, n = n0 + tx;
        if (k < K && n < N) t[ty + i*8][tx] = W[(size_t)k * N + n];
    }
    __syncthreads();
    #pragma unroll
    for (int i = 0; i < 4; i++) {
        int n = n0 + ty + i * 8, k = k0 + tx;
        if (k < K && n < N) {
            __half h, l;
            f16_split(t[tx][ty + i*8], h, l);
            size_t o = (size_t)off + (size_t)n * K + k;
            Wh[o] = h;
            Wl[o] = l;
        }
    }
}

// ============ split-fp16x2 (3-pass) m16n8k16 warp-MMA GEMM ==================
// (unchanged from R12 — proven 624us config, 2 CTAs/SM)
template<int BN, int MODE>
__global__ void __launch_bounds__(256, 2) mma_gemm(
    const float* __restrict__ A,
    const __half* __restrict__ Ahg, const __half* __restrict__ Alg,
    const __half* __restrict__ Wh, const __half* __restrict__ Wl,
    const float* __restrict__ bias, float* __restrict__ C,
    int M, int N, int K,
    const float* __restrict__ alpha, const float* __restrict__ dw,
    const float* __restrict__ db)
{
    constexpr int PKA = 20;
    constexpr int PKB = 20;
    constexpr int WN = BN / 2;
    constexpr int NT8 = WN / 8;
    constexpr int PRAW = 36;
    constexpr int AST = (MODE == 0) ? 2 : 1;

    extern __shared__ uint32_t smw[];
    uint32_t* rawA = smw;
    uint32_t* AhP  = smw + ((MODE == 1) ? 2 * 128 * PRAW : 0);
    uint32_t* AlP  = AhP + AST * 128 * PKA;
    uint32_t* BhP  = AlP + AST * 128 * PKA;
    uint32_t* BlP  = BhP + 2 * BN * PKB;

    uint32_t sbase  = smem_u32(smw);
    uint32_t rawA_b = sbase;
    uint32_t AhP_b  = sbase + (uint32_t)(((MODE == 1) ? 2*128*PRAW : 0) * 4);
    uint32_t AlP_b  = AhP_b + (uint32_t)(AST * 128 * PKA * 4);
    uint32_t BhP_b  = AlP_b + (uint32_t)(AST * 128 * PKA * 4);
    uint32_t BlP_b  = BhP_b + (uint32_t)(2 * BN * PKB * 4);

    int tid = threadIdx.x, wid = tid >> 5, lane = tid & 31;
    int wm = (wid & 3) * 32, wn = (wid >> 2) * WN;
    int g4 = lane >> 2, t4 = lane & 3;
    int m0 = blockIdx.y * 128, n0 = blockIdx.x * BN;
    float a0s = (MODE == 1) ? __ldg(alpha) : 0.f;

    float acc[2][NT8][4];
    #pragma unroll
    for (int i = 0; i < 2; i++)
        #pragma unroll
        for (int j = 0; j < NT8; j++)
            #pragma unroll
            for (int t = 0; t < 4; t++) acc[i][j][t] = 0.f;

    int NC = (K + 31) / 32;

    auto issue = [&](int c) {
        int s = c & 1;
        int k0 = c * 32;
        if (MODE == 1) {
            #pragma unroll
            for (int it = 0; it < 4; it++) {
                int idx = tid + it * 256;
                int r = idx >> 3, f4 = idx & 7;
                int gm = m0 + r, gk = k0 + f4 * 4;
                bool v = (gm < M) && (gk < K);
                const float* src = v ? (A + (size_t)gm * K + gk) : A;
                cpa16(rawA_b + (uint32_t)((s*128*PRAW + r*PRAW + f4*4) * 4),
                      src, v ? 16u : 0u);
            }
        } else {
            #pragma unroll
            for (int it = 0; it < 2; it++) {
                int idx = tid + it * 256;
                int r = idx >> 2, f = idx & 3;
                int gm = m0 + r, gk = k0 + f * 8;
                bool v = (gm < M) && (gk < K);
                size_t go = (size_t)gm * K + gk;
                uint32_t so = (uint32_t)((s*128*PKA + r*PKA + f*4) * 4);
                cpa16(AhP_b + so, v ? (const void*)(Ahg + go) : (const void*)Ahg, v ? 16u : 0u);
                cpa16(AlP_b + so, v ? (const void*)(Alg + go) : (const void*)Alg, v ? 16u : 0u);
            }
        }
        constexpr int BGRP = BN * 4;
        #pragma unroll
        for (int it = 0; it < (BGRP + 255) / 256; it++) {
            int idx = tid + it * 256;
            if (idx < BGRP) {
                int nr = idx >> 2, q = idx & 3;
                int gn = n0 + nr, gk = k0 + q * 8;
                bool v = (gk < K);
                size_t go = (size_t)gn * K + gk;
                uint32_t so = (uint32_t)((s*BN*PKB + nr*PKB + q*4) * 4);
                cpa16(BhP_b + so, v ? (const void*)(Wh + go) : (const void*)Wh, v ? 16u : 0u);
                cpa16(BlP_b + so, v ? (const void*)(Wl + go) : (const void*)Wl, v ? 16u : 0u);
            }
        }
        asm volatile("cp.async.commit_group;" ::: "memory");
    };

    auto transform = [&](int c) {
        int s = c & 1;
        int k0 = c * 32;
        #pragma unroll
        for (int it = 0; it < 4; it++) {
            int idx = tid + it * 256;
            int r = idx >> 3, f4 = idx & 7;
            float4 v = *(const float4*)(rawA + s * 128 * PRAW + r * PRAW + f4 * 4);
            int gk = k0 + f4 * 4;
            float4 w4 = *(const float4*)(dw + gk);
            float4 b4 = *(const float4*)(db + gk);
            v.x = tanhf(a0s * v.x) * w4.x + b4.x;
            v.y = tanhf(a0s * v.y) * w4.y + b4.y;
            v.z = tanhf(a0s * v.z) * w4.z + b4.z;
            v.w = tanhf(a0s * v.w) * w4.w + b4.w;
            __half hx, lx, hy, ly, hz, lz, hw, lw;
            f16_split(v.x, hx, lx);
            f16_split(v.y, hy, ly);
            f16_split(v.z, hz, lz);
            f16_split(v.w, hw, lw);
            __half2 H0 = __halves2half2(hx, hy), H1 = __halves2half2(hz, hw);
            __half2 L0 = __halves2half2(lx, ly), L1 = __halves2half2(lz, lw);
            int wb = r * PKA + f4 * 2;
            *(uint2*)(AhP + wb) = make_uint2(*(uint32_t*)&H0, *(uint32_t*)&H1);
            *(uint2*)(AlP + wb) = make_uint2(*(uint32_t*)&L0, *(uint32_t*)&L1);
        }
    };

    auto compute = [&](int c) {
        int s = c & 1;
        const uint32_t* Ahb = AhP + ((MODE == 0) ? s * 128 * PKA : 0);
        const uint32_t* Alb = AlP + ((MODE == 0) ? s * 128 * PKA : 0);
        const uint32_t* Bhb = BhP + s * BN * PKB;
        const uint32_t* Blb = BlP + s * BN * PKB;
        #pragma unroll
        for (int kk = 0; kk < 2; kk++) {
            int kw = kk * 8;
            uint32_t ah[2][4], al[2][4];
            #pragma unroll
            for (int mt = 0; mt < 2; mt++) {
                int r0 = (wm + mt * 16 + g4) * PKA + kw + t4;
                ah[mt][0] = Ahb[r0];
                ah[mt][1] = Ahb[r0 + 8 * PKA];
                ah[mt][2] = Ahb[r0 + 4];
                ah[mt][3] = Ahb[r0 + 8 * PKA + 4];
                al[mt][0] = Alb[r0];
                al[mt][1] = Alb[r0 + 8 * PKA];
                al[mt][2] = Alb[r0 + 4];
                al[mt][3] = Alb[r0 + 8 * PKA + 4];
            }
            uint32_t bh[NT8][2], bl[NT8][2];
            #pragma unroll
            for (int nt = 0; nt < NT8; nt++) {
                int nb = (wn + nt * 8 + g4) * PKB + kw + t4;
                bh[nt][0] = Bhb[nb];
                bh[nt][1] = Bhb[nb + 4];
                bl[nt][0] = Blb[nb];
                bl[nt][1] = Blb[nb + 4];
            }
            #pragma unroll
            for (int mt = 0; mt < 2; mt++)
                #pragma unroll
                for (int nt = 0; nt < NT8; nt++) {
                    mma16(acc[mt][nt], ah[mt][0], ah[mt][1], ah[mt][2], ah[mt][3],
                          bh[nt][0], bh[nt][1]);
                    mma16(acc[mt][nt], ah[mt][0], ah[mt][1], ah[mt][2], ah[mt][3],
                          bl[nt][0], bl[nt][1]);
                    mma16(acc[mt][nt], al[mt][0], al[mt][1], al[mt][2], al[mt][3],
                          bh[nt][0], bh[nt][1]);
                }
        }
    };

    issue(0);
    for (int c = 0; c < NC; c++) {
        asm volatile("cp.async.wait_group 0;" ::: "memory");
        __syncthreads();
        if (c + 1 < NC) issue(c + 1);
        if (MODE == 1) {
            transform(c);
            __syncthreads();
        }
        compute(c);
    }

    #pragma unroll
    for (int mt = 0; mt < 2; mt++) {
        int gr = m0 + wm + mt * 16 + g4;
        #pragma unroll
        for (int nt = 0; nt < NT8; nt++) {
            int gc = n0 + wn + nt * 8 + t4 * 2;
            float2 bv = *(const float2*)(bias + gc);
            if (gr < M) {
                float2 o = make_float2(acc[mt][nt][0] + bv.x, acc[mt][nt][1] + bv.y);
                *(float2*)(C + (size_t)gr * N + gc) = o;
            }
            if (gr + 8 < M) {
                float2 o = make_float2(acc[mt][nt][2] + bv.x, acc[mt][nt][3] + bv.y);
                *(float2*)(C + (size_t)(gr + 8) * N + gc) = o;
            }
        }
    }
}

// ---------------- prep: combined conv kernel --------------------------------
__global__ void prep_kernel(const float* __restrict__ A, const float* __restrict__ Bp,
                            const float* __restrict__ Cp, const float* __restrict__ cw)
{
    __shared__ float U[DU][NSTATE];
    __shared__ float gk[DU];
    __shared__ float sC[NSTATE];
    int tid = threadIdx.x;
    int e = blockIdx.x;
    if (tid < 32) {
        int i = tid & 15;
        float u = 1.f / (1.f + expf(-Bp[i]));
        for (int d = 0; d < DU; d++) {
            if (tid < 16) U[d][i] = u;
            float nu = 0.f;
            #pragma unroll
            for (int j = 0; j < 16; j++)
                nu += A[i*16 + j] * __shfl_sync(0xFFFFFFFFu, u, j);
            u = nu;
        }
    }
    if (tid < 16) sC[tid] = 1.f / (1.f + expf(-Cp[e*16 + tid]));
    __syncthreads();
    for (int d = tid; d < DU; d += blockDim.x) {
        float s = 0.f;
        #pragma unroll
        for (int i = 0; i < 16; i++) s += sC[i] * U[d][i];
        gk[d] = s;
    }
    __syncthreads();
    for (int dd = tid; dd < DK; dd += blockDim.x) {
        float s = 0.f;
        #pragma unroll
        for (int d1 = 0; d1 < 4; d1++) {
            int d2 = dd - d1;
            if (d2 >= 0 && d2 < DU) s += cw[e*4 + (3 - d1)] * gk[d2];
        }
        g_K[e*DK + dd] = s;
    }
}

// ---------- row L2-normalize -> pre-split fp16 hi/lo planes (vectorized) ----
__global__ void norm_kernel(const float* __restrict__ xp,
                            __half* __restrict__ xh, __half* __restrict__ xl)
{
    int lane = threadIdx.x & 31;
    int row = blockIdx.x * 8 + (threadIdx.x >> 5);
    const float4* p4 = (const float4*)(xp + (size_t)row * EE);   // 84 float4
    float s = 0.f;
    float4 buf[3];
    #pragma unroll
    for (int i = 0; i < 3; i++) {
        int idx = lane + 32 * i;
        if (idx < 84) {
            float4 v = p4[idx];
            buf[i] = v;
            s += v.x*v.x + v.y*v.y + v.z*v.z + v.w*v.w;
        }
    }
    #pragma unroll
    for (int o = 16; o > 0; o >>= 1) s += __shfl_xor_sync(0xFFFFFFFFu, s, o);
    float inv = 1.f / fmaxf(sqrtf(s), 1e-12f);
    __half2* h2 = (__half2*)(xh + (size_t)row * EE);
    __half2* l2 = (__half2*)(xl + (size_t)row * EE);
    #pragma unroll
    for (int i = 0; i < 3; i++) {
        int idx = lane + 32 * i;
        if (idx < 84) {
            float4 v = buf[i];
            v.x *= inv; v.y *= inv; v.z *= inv; v.w *= inv;
            __half ha, la, hb, lb, hc, lc, hd, ld;
            f16_split(v.x, ha, la);
            f16_split(v.y, hb, lb);
            f16_split(v.z, hc, lc);
            f16_split(v.w, hd, ld);
            h2[idx*2 + 0] = __halves2half2(ha, hb);
            h2[idx*2 + 1] = __halves2half2(hc, hd);
            l2[idx*2 + 0] = __halves2half2(la, lb);
            l2[idx*2 + 1] = __halves2half2(lc, ld);
        }
    }
}

// ---------------- attention (float4 loads) ----------------------------------
__global__ void attn_kernel(const float* __restrict__ qkv,
                            float* __restrict__ att, float* __restrict__ imp)
{
    __shared__ float sq[4][E3];
    __shared__ float sc[4][36];
    __shared__ int   gb[4][NH];
    int wid = threadIdx.x >> 5, lane = threadIdx.x & 31;
    int n = blockIdx.x * 4 + wid;
    const float4* row4 = (const float4*)(qkv + (size_t)n * E3);   // 252 float4
    float4* s4 = (float4*)sq[wid];
    #pragma unroll
    for (int i = 0; i < 8; i++) {
        int idx = lane + 32 * i;
        if (idx < 252) s4[idx] = row4[idx];
    }
    float* s = sq[wid];
    __syncwarp();
    for (int p = lane; p < 36; p += 32) {
        int h = p / 6, g = p - h*6;
        const float* qp = s + h*HDIM;
        const float* kp = s + EE + g*HDIM;
        float d = 0.f;
        #pragma unroll
        for (int t = 0; t < HDIM; t++) d += qp[t] * kp[t];
        sc[wid][p] = d;
    }
    __syncwarp();
    if (lane < NH) {
        float best = sc[wid][lane*6]; int bg = 0;
        #pragma unroll
        for (int g = 1; g < 6; g++) {
            float v = sc[wid][lane*6 + g];
            if (v > best) { best = v; bg = g; }   // strict > : jax tie -> lowest idx
        }
        gb[wid][lane] = bg;
    }
    __syncwarp();
    float acc = 0.f;
    for (int e = lane; e < EE; e += 32) {
        int h = e % NH, d = e / NH;
        float v = s[2*EE + gb[wid][h]*HDIM + d];
        att[(size_t)n*EE + e] = v;
        acc += v*v;
    }
    #pragma unroll
    for (int o = 16; o > 0; o >>= 1) acc += __shfl_xor_sync(0xFFFFFFFFu, acc, o);
    if (lane == 0) imp[n] = sqrtf(acc);
}

// ---------------- inverse index clear ----------------------------------------
__global__ void inv_clear_kernel()
{
    int i = blockIdx.x * 1024 + threadIdx.x;
    g_inv[i] = -1;
}

// ---------------- top-819 per batch + inverse map ----------------------------
__global__ void topk_kernel(const float* __restrict__ imp, int* __restrict__ idxout)
{
    __shared__ unsigned long long key[LL];
    int b = blockIdx.x;
    for (int i = threadIdx.x; i < LL; i += blockDim.x) {
        unsigned fb = __float_as_uint(imp[b*LL + i]);
        key[i] = ((unsigned long long)(0xFFFFFFFFu - fb) << 32) | (unsigned)i;
    }
    __syncthreads();
    for (int k = 2; k <= LL; k <<= 1)
        for (int j = k >> 1; j > 0; j >>= 1) {
            for (int i = threadIdx.x; i < LL; i += blockDim.x) {
                int ixj = i ^ j;
                if (ixj > i) {
                    bool up = ((i & k) == 0);
                    unsigned long long a = key[i], c = key[ixj];
                    if ((a > c) == up) { key[i] = c; key[ixj] = a; }
                }
            }
            __syncthreads();
        }
    for (int i = threadIdx.x; i < KC; i += blockDim.x) {
        int pos = (int)(key[i] & 0xFFFFFFFFu);
        idxout[b*KC + i] = pos;
        g_inv[b*LL + pos] = b*KC + i;     // global xproc row
    }
}

// -------- fused gather + 67-tap causal conv -> fp16 ys planes ---------------
__global__ void __launch_bounds__(224) conv_kernel(const float* __restrict__ att,
                                                   const int* __restrict__ idx,
                                                   __half* __restrict__ ysh,
                                                   __half* __restrict__ ysl)
{
    const int ET = 56, JT = 64, WIN = JT + DK - 1;
    __shared__ float sp[ET][WIN + 1];
    __shared__ float Ks[ET][DK + 1];
    __shared__ int   sidx[WIN];
    int et = blockIdx.x, jt = blockIdx.y, b = blockIdx.z;
    int e0 = et * ET, j0 = jt * JT;
    int tid = threadIdx.x;

    for (int w = tid; w < WIN; w += 224) {
        int j = j0 - (DK - 1) + w;
        sidx[w] = (j >= 0 && j < KC) ? idx[b*KC + j] : -1;
    }
    for (int i = tid; i < ET*DK; i += 224) {
        int ee = i / DK, d = i - ee*DK;
        Ks[ee][d] = g_K[(e0 + ee)*DK + d];
    }
    __syncthreads();
    for (int i = tid; i < WIN*ET; i += 224) {
        int w = i / ET, ee = i - w*ET;
        int pos = sidx[w];
        sp[ee][w] = (pos >= 0) ? att[((size_t)b*LL + pos)*EE + e0 + ee] : 0.f;
    }
    __syncthreads();

    int ee = tid % ET, jg = tid / ET;
    float acc[16];
    #pragma unroll
    for (int t = 0; t < 16; t++) acc[t] = 0.f;
    int wbase = (DK - 1) + jg*16;
    for (int d = 0; d < DK; d++) {
        float kv = Ks[ee][d];
        #pragma unroll
        for (int t = 0; t < 16; t++)
            acc[t] += kv * sp[ee][wbase + t - d];
    }
    #pragma unroll
    for (int t = 0; t < 16; t++) {
        int j = j0 + jg*16 + t;
        if (j < KC) {
            __half h, l;
            f16_split(acc[t], h, l);
            size_t o = ((size_t)b*KC + j)*EE + e0 + ee;
            ysh[o] = h;
            ysl[o] = l;
        }
    }
}

// ------------- fused output: out = x + (selected ? xproc : 0) ---------------
__global__ void out_kernel(const float4* __restrict__ x,
                           const float4* __restrict__ xproc,
                           float4* __restrict__ out)
{
    int row = blockIdx.x;                  // 0..NN-1
    int j = g_inv[row];
    const float4* xr = x + (size_t)row * 128;
    float4* o = out + (size_t)row * 128;
    int c = threadIdx.x;                   // 128 threads, one float4 each
    float4 v = xr[c];
    if (j >= 0) {
        float4 p = xproc[(size_t)j * 128 + c];
        v.x += p.x; v.y += p.y; v.z += p.z; v.w += p.w;
    }
    o[c] = v;
}

// ---------------- launch ----------------------------------------------------
extern "C" void kernel_launch(void* const* d_in, const int* in_sizes, int n_in,
                              void* d_out, int out_size)
{
    const float* x      = (const float*)d_in[0];
    const float* alpha  = (const float*)d_in[1];
    const float* dyt_w  = (const float*)d_in[2];
    const float* dyt_b  = (const float*)d_in[3];
    const float* W_in   = (const float*)d_in[4];
    const float* b_in   = (const float*)d_in[5];
    const float* W_qkv  = (const float*)d_in[6];
    const float* b_qkv  = (const float*)d_in[7];
    const float* conv_w = (const float*)d_in[8];
    const float* A      = (const float*)d_in[9];
    const float* Bp     = (const float*)d_in[10];
    const float* Cp     = (const float*)d_in[11];
    const float* W_out  = (const float*)d_in[12];
    const float* b_out  = (const float*)d_in[13];
    float* out = (float*)d_out;

    float *xp, *qkv, *att, *imp, *xproc;
    __half *wh, *wl, *xph, *xpl, *ysh, *ysl;
    int *idx;
    cudaGetSymbolAddress((void**)&xp,    g_xp);
    cudaGetSymbolAddress((void**)&qkv,   g_qkv);
    cudaGetSymbolAddress((void**)&att,   g_att);
    cudaGetSymbolAddress((void**)&imp,   g_imp);
    cudaGetSymbolAddress((void**)&idx,   g_idx);
    cudaGetSymbolAddress((void**)&xproc, g_xproc);
    cudaGetSymbolAddress((void**)&wh,    g_Wh);
    cudaGetSymbolAddress((void**)&wl,    g_Wl);
    cudaGetSymbolAddress((void**)&xph,   g_xph);
    cudaGetSymbolAddress((void**)&xpl,   g_xpl);
    cudaGetSymbolAddress((void**)&ysh,   g_ysh);
    cudaGetSymbolAddress((void**)&ysl,   g_ysl);

    const int SM_M1  = (2*128*36 + 2*128*20 + 2*2*112*20) * 4;
    const int SM_M0A = (2*2*128*20 + 2*2*112*20) * 4;
    const int SM_M0B = (2*2*128*20 + 2*2*128*20) * 4;
    cudaFuncSetAttribute(mma_gemm<112,1>, cudaFuncAttributeMaxDynamicSharedMemorySize, SM_M1);
    cudaFuncSetAttribute(mma_gemm<112,0>, cudaFuncAttributeMaxDynamicSharedMemorySize, SM_M0A);
    cudaFuncSetAttribute(mma_gemm<128,0>, cudaFuncAttributeMaxDynamicSharedMemorySize, SM_M0B);

    // launch order: qkv GEMM at capture index 3 (matches ncu -s 5 -c 1 slot)
    // 0) all weight planes: transpose + fp16 split
    wsplit_t_kernel<<<dim3(16, 32, 3), dim3(32, 8)>>>(W_in, W_qkv, W_out, wh, wl);
    // 1) xp = dyt(x) @ W_in + b_in   [32768,512]x[512,336]  (MODE1)
    mma_gemm<112,1><<<dim3(3, NN/128), 256, SM_M1>>>(x, nullptr, nullptr,
                                                     wh + OFF_WIN, wl + OFF_WIN,
                                                     b_in, xp, NN, EE, DIMC,
                                                     alpha, dyt_w, dyt_b);
    // 2) row-normalize -> pre-split xpn planes (vectorized)
    norm_kernel<<<NN/8, 256>>>(xp, xph, xpl);
    // 3) qkv = xpn @ W_qkv + b_qkv  [32768,336]x[336,1008]  (MODE0)  <- profiled
    mma_gemm<112,0><<<dim3(9, NN/128), 256, SM_M0A>>>(nullptr, xph, xpl,
                                                      wh + OFF_WQKV, wl + OFF_WQKV,
                                                      b_qkv, qkv, NN, E3, EE,
                                                      alpha, dyt_w, dyt_b);
    // 4) scan->conv kernel precompute + inverse-map clear
    prep_kernel<<<EE, 128>>>(A, Bp, Cp, conv_w);
    inv_clear_kernel<<<NN/1024, 1024>>>();
    // 5) sparse attention (kh=1 -> argmax gather) + importance
    attn_kernel<<<NN/4, 128>>>(qkv, att, imp);
    // 6) exact sorted top-819 per batch (+ inverse map)
    topk_kernel<<<BB, 1024>>>(imp, idx);
    // 7) gather + combined dconv*scan causal convolution -> ys planes
    conv_kernel<<<dim3(EE/56, (KC + 63)/64, BB), 224>>>(att, idx, ysh, ysl);
    // 8) xproc = ys @ W_out + b_out  [6552,336]x[336,512]  (MODE0)
    mma_gemm<128,0><<<dim3(4, (BB*KC + 127)/128), 256, SM_M0B>>>(nullptr, ysh, ysl,
                                                                 wh + OFF_WOUT, wl + OFF_WOUT,
                                                                 b_out, xproc, BB*KC, DIMC, EE,
                                                                 alpha, dyt_w, dyt_b);
    // 9) fused residual + scatter
    out_kernel<<<NN, 128>>>((const float4*)x, (const float4*)xproc, (float4*)out);
}

// round 14
// speedup vs baseline: 2.0488x; 1.0336x over previous
#include <cuda_runtime.h>
#include <cuda_fp16.h>
#include <cstdint>

#define DIMC 512
#define EE 336
#define E3 1008
#define NSTATE 16
#define NH 6
#define HDIM 56
#define BB 8
#define LL 4096
#define NN (BB*LL)        // 32768 tokens
#define KC 819
#define DU 64             // truncated scan kernel length
#define DK 67             // combined (scan * dconv) kernel length

// weight plane offsets (half elements) — transposed [n][K] layout
#define OFF_WIN  0
#define OFF_WQKV (512*336)
#define OFF_WOUT (512*336 + 336*1008)
#define WPL_TOTAL (512*336 + 336*1008 + 336*512)

// ---------------- scratch (static device memory; no allocs allowed) ----------
__device__ float  g_xp[(size_t)NN*EE];
__device__ float  g_qkv[(size_t)NN*E3];
__device__ __half g_att[(size_t)NN*EE];     // fp16: only consumer is conv
__device__ float  g_imp[NN];
__device__ int    g_idx[BB*KC];
__device__ int    g_inv[NN];                // row -> global xproc row (or -1)
__device__ float  g_xproc[(size_t)BB*KC*DIMC];
__device__ float  g_K[EE*DK];
__device__ __half g_Wh[WPL_TOTAL];          // W^T hi plane [n][K]
__device__ __half g_Wl[WPL_TOTAL];          // W^T lo plane
__device__ __half g_xph[(size_t)NN*EE];     // xpn hi plane [row][k]
__device__ __half g_xpl[(size_t)NN*EE];
__device__ __half g_ysh[(size_t)BB*KC*EE];  // ys fp16 (hi only; GEMM3 is 1-pass)

// ============================ helpers =======================================
__device__ __forceinline__ uint32_t smem_u32(const void* p) {
    uint32_t a;
    asm("{ .reg .u64 t; cvta.to.shared.u64 t, %1; cvt.u32.u64 %0, t; }" : "=r"(a) : "l"(p));
    return a;
}
// fp16 2-term split: v = hi + lo + O(2^-22 v)
__device__ __forceinline__ void f16_split(float v, __half& h, __half& l) {
    h = __float2half_rn(v);
    l = __float2half_rn(v - __half2float(h));
}
__device__ __forceinline__ void mma16(float* c, uint32_t a0, uint32_t a1,
                                      uint32_t a2, uint32_t a3,
                                      uint32_t b0, uint32_t b1) {
    asm volatile("mma.sync.aligned.m16n8k16.row.col.f32.f16.f16.f32 "
        "{%0,%1,%2,%3}, {%4,%5,%6,%7}, {%8,%9}, {%0,%1,%2,%3};"
        : "+f"(c[0]), "+f"(c[1]), "+f"(c[2]), "+f"(c[3])
        : "r"(a0), "r"(a1), "r"(a2), "r"(a3), "r"(b0), "r"(b1));
}
__device__ __forceinline__ void cpa16(uint32_t dst, const void* src, uint32_t sz) {
    asm volatile("cp.async.ca.shared.global [%0], [%1], 16, %2;"
        :: "r"(dst), "l"(src), "r"(sz));
}

// ------- weight split: W[K,N] -> W^T fp16 hi/lo planes [n][k] (tiled) -------
__global__ void wsplit_t_kernel(const float* __restrict__ W0,
                                const float* __restrict__ W1,
                                const float* __restrict__ W2,
                                __half* __restrict__ Wh, __half* __restrict__ Wl)
{
    __shared__ float t[32][33];
    int z = blockIdx.z;
    const float* W = (z == 0) ? W0 : ((z == 1) ? W1 : W2);
    int K = (z == 0) ? 512 : 336;
    int N = (z == 0) ? 336 : ((z == 1) ? 1008 : 512);
    int off = (z == 0) ? OFF_WIN : ((z == 1) ? OFF_WQKV : OFF_WOUT);
    int k0 = blockIdx.x * 32, n0 = blockIdx.y * 32;
    if (k0 >= K || n0 >= N) return;
    int tx = threadIdx.x, ty = threadIdx.y;   // (32, 8)
    #pragma unroll
    for (int i = 0; i < 4; i++) {
        int k = k0 + ty + i * 8, n = n0 + tx;
        if (k < K && n < N) t[ty + i*8][tx] = W[(size_t)k * N + n];
    }
    __syncthreads();
    #pragma unroll
    for (int i = 0; i < 4; i++) {
        int n = n0 + ty + i * 8, k = k0 + tx;
        if (k < K && n < N) {
            __half h, l;
            f16_split(t[tx][ty + i*8], h, l);
            size_t o = (size_t)off + (size_t)n * K + k;
            Wh[o] = h;
            Wl[o] = l;
        }
    }
}

// ============ split-fp16 warp-MMA GEMM ======================================
// C[M,N] = op(A)[M,K] @ W[K,N] + bias.  K-chunk 32 (2 k16 steps), 2-stage
// cp.async pipeline, 2 CTAs/SM.  8 warps (4M x 2N), warp tile 32 x BN/2.
// MODE 1: A raw fp32 streamed; DyT(tanh)+split transform in-kernel (3-pass).
// MODE 0: A pre-split hi/lo half planes streamed directly (3-pass).
// HIONLY 1 (with MODE 0): hi planes only, single hh MMA pass (pure fp16).
template<int BN, int MODE, int HIONLY>
__global__ void __launch_bounds__(256, 2) mma_gemm(
    const float* __restrict__ A,
    const __half* __restrict__ Ahg, const __half* __restrict__ Alg,
    const __half* __restrict__ Wh, const __half* __restrict__ Wl,
    const float* __restrict__ bias, float* __restrict__ C,
    int M, int N, int K,
    const float* __restrict__ alpha, const float* __restrict__ dw,
    const float* __restrict__ db)
{
    constexpr int PKA = 20;
    constexpr int PKB = 20;
    constexpr int WN = BN / 2;
    constexpr int NT8 = WN / 8;
    constexpr int PRAW = 36;
    constexpr int AST = (MODE == 0) ? 2 : 1;
    constexpr int NPL = HIONLY ? 1 : 2;     // planes held in smem

    extern __shared__ uint32_t smw[];
    uint32_t* rawA = smw;
    uint32_t* AhP  = smw + ((MODE == 1) ? 2 * 128 * PRAW : 0);
    uint32_t* AlP  = AhP + AST * 128 * PKA;                 // unused if HIONLY
    uint32_t* BhP  = AhP + NPL * AST * 128 * PKA;
    uint32_t* BlP  = BhP + 2 * BN * PKB;                    // unused if HIONLY

    uint32_t sbase  = smem_u32(smw);
    uint32_t rawA_b = sbase;
    uint32_t AhP_b  = sbase + (uint32_t)(((MODE == 1) ? 2*128*PRAW : 0) * 4);
    uint32_t AlP_b  = AhP_b + (uint32_t)(AST * 128 * PKA * 4);
    uint32_t BhP_b  = AhP_b + (uint32_t)(NPL * AST * 128 * PKA * 4);
    uint32_t BlP_b  = BhP_b + (uint32_t)(2 * BN * PKB * 4);

    int tid = threadIdx.x, wid = tid >> 5, lane = tid & 31;
    int wm = (wid & 3) * 32, wn = (wid >> 2) * WN;
    int g4 = lane >> 2, t4 = lane & 3;
    int m0 = blockIdx.y * 128, n0 = blockIdx.x * BN;
    float a0s = (MODE == 1) ? __ldg(alpha) : 0.f;

    float acc[2][NT8][4];
    #pragma unroll
    for (int i = 0; i < 2; i++)
        #pragma unroll
        for (int j = 0; j < NT8; j++)
            #pragma unroll
            for (int t = 0; t < 4; t++) acc[i][j][t] = 0.f;

    int NC = (K + 31) / 32;

    auto issue = [&](int c) {
        int s = c & 1;
        int k0 = c * 32;
        if (MODE == 1) {
            #pragma unroll
            for (int it = 0; it < 4; it++) {
                int idx = tid + it * 256;
                int r = idx >> 3, f4 = idx & 7;
                int gm = m0 + r, gk = k0 + f4 * 4;
                bool v = (gm < M) && (gk < K);
                const float* src = v ? (A + (size_t)gm * K + gk) : A;
                cpa16(rawA_b + (uint32_t)((s*128*PRAW + r*PRAW + f4*4) * 4),
                      src, v ? 16u : 0u);
            }
        } else {
            #pragma unroll
            for (int it = 0; it < 2; it++) {
                int idx = tid + it * 256;
                int r = idx >> 2, f = idx & 3;
                int gm = m0 + r, gk = k0 + f * 8;
                bool v = (gm < M) && (gk < K);
                size_t go = (size_t)gm * K + gk;
                uint32_t so = (uint32_t)((s*128*PKA + r*PKA + f*4) * 4);
                cpa16(AhP_b + so, v ? (const void*)(Ahg + go) : (const void*)Ahg, v ? 16u : 0u);
                if (!HIONLY)
                    cpa16(AlP_b + so, v ? (const void*)(Alg + go) : (const void*)Alg, v ? 16u : 0u);
            }
        }
        constexpr int BGRP = BN * 4;
        #pragma unroll
        for (int it = 0; it < (BGRP + 255) / 256; it++) {
            int idx = tid + it * 256;
            if (idx < BGRP) {
                int nr = idx >> 2, q = idx & 3;
                int gn = n0 + nr, gk = k0 + q * 8;
                bool v = (gk < K);
                size_t go = (size_t)gn * K + gk;
                uint32_t so = (uint32_t)((s*BN*PKB + nr*PKB + q*4) * 4);
                cpa16(BhP_b + so, v ? (const void*)(Wh + go) : (const void*)Wh, v ? 16u : 0u);
                if (!HIONLY)
                    cpa16(BlP_b + so, v ? (const void*)(Wl + go) : (const void*)Wl, v ? 16u : 0u);
            }
        }
        asm volatile("cp.async.commit_group;" ::: "memory");
    };

    auto transform = [&](int c) {
        int s = c & 1;
        int k0 = c * 32;
        #pragma unroll
        for (int it = 0; it < 4; it++) {
            int idx = tid + it * 256;
            int r = idx >> 3, f4 = idx & 7;
            float4 v = *(const float4*)(rawA + s * 128 * PRAW + r * PRAW + f4 * 4);
            int gk = k0 + f4 * 4;
            float4 w4 = *(const float4*)(dw + gk);
            float4 b4 = *(const float4*)(db + gk);
            v.x = tanhf(a0s * v.x) * w4.x + b4.x;
            v.y = tanhf(a0s * v.y) * w4.y + b4.y;
            v.z = tanhf(a0s * v.z) * w4.z + b4.z;
            v.w = tanhf(a0s * v.w) * w4.w + b4.w;
            __half hx, lx, hy, ly, hz, lz, hw, lw;
            f16_split(v.x, hx, lx);
            f16_split(v.y, hy, ly);
            f16_split(v.z, hz, lz);
            f16_split(v.w, hw, lw);
            __half2 H0 = __halves2half2(hx, hy), H1 = __halves2half2(hz, hw);
            __half2 L0 = __halves2half2(lx, ly), L1 = __halves2half2(lz, lw);
            int wb = r * PKA + f4 * 2;
            *(uint2*)(AhP + wb) = make_uint2(*(uint32_t*)&H0, *(uint32_t*)&H1);
            *(uint2*)(AlP + wb) = make_uint2(*(uint32_t*)&L0, *(uint32_t*)&L1);
        }
    };

    auto compute = [&](int c) {
        int s = c & 1;
        const uint32_t* Ahb = AhP + ((MODE == 0) ? s * 128 * PKA : 0);
        const uint32_t* Alb = AlP + ((MODE == 0) ? s * 128 * PKA : 0);
        const uint32_t* Bhb = BhP + s * BN * PKB;
        const uint32_t* Blb = BlP + s * BN * PKB;
        #pragma unroll
        for (int kk = 0; kk < 2; kk++) {
            int kw = kk * 8;
            uint32_t ah[2][4], al[2][4];
            #pragma unroll
            for (int mt = 0; mt < 2; mt++) {
                int r0 = (wm + mt * 16 + g4) * PKA + kw + t4;
                ah[mt][0] = Ahb[r0];
                ah[mt][1] = Ahb[r0 + 8 * PKA];
                ah[mt][2] = Ahb[r0 + 4];
                ah[mt][3] = Ahb[r0 + 8 * PKA + 4];
                if (!HIONLY) {
                    al[mt][0] = Alb[r0];
                    al[mt][1] = Alb[r0 + 8 * PKA];
                    al[mt][2] = Alb[r0 + 4];
                    al[mt][3] = Alb[r0 + 8 * PKA + 4];
                }
            }
            uint32_t bh[NT8][2], bl[NT8][2];
            #pragma unroll
            for (int nt = 0; nt < NT8; nt++) {
                int nb = (wn + nt * 8 + g4) * PKB + kw + t4;
                bh[nt][0] = Bhb[nb];
                bh[nt][1] = Bhb[nb + 4];
                if (!HIONLY) {
                    bl[nt][0] = Blb[nb];
                    bl[nt][1] = Blb[nb + 4];
                }
            }
            #pragma unroll
            for (int mt = 0; mt < 2; mt++)
                #pragma unroll
                for (int nt = 0; nt < NT8; nt++) {
                    mma16(acc[mt][nt], ah[mt][0], ah[mt][1], ah[mt][2], ah[mt][3],
                          bh[nt][0], bh[nt][1]);
                    if (!HIONLY) {
                        mma16(acc[mt][nt], ah[mt][0], ah[mt][1], ah[mt][2], ah[mt][3],
                              bl[nt][0], bl[nt][1]);
                        mma16(acc[mt][nt], al[mt][0], al[mt][1], al[mt][2], al[mt][3],
                              bh[nt][0], bh[nt][1]);
                    }
                }
        }
    };

    issue(0);
    for (int c = 0; c < NC; c++) {
        asm volatile("cp.async.wait_group 0;" ::: "memory");
        __syncthreads();
        if (c + 1 < NC) issue(c + 1);
        if (MODE == 1) {
            transform(c);
            __syncthreads();
        }
        compute(c);
    }

    #pragma unroll
    for (int mt = 0; mt < 2; mt++) {
        int gr = m0 + wm + mt * 16 + g4;
        #pragma unroll
        for (int nt = 0; nt < NT8; nt++) {
            int gc = n0 + wn + nt * 8 + t4 * 2;
            float2 bv = *(const float2*)(bias + gc);
            if (gr < M) {
                float2 o = make_float2(acc[mt][nt][0] + bv.x, acc[mt][nt][1] + bv.y);
                *(float2*)(C + (size_t)gr * N + gc) = o;
            }
            if (gr + 8 < M) {
                float2 o = make_float2(acc[mt][nt][2] + bv.x, acc[mt][nt][3] + bv.y);
                *(float2*)(C + (size_t)(gr + 8) * N + gc) = o;
            }
        }
    }
}

// ---------------- prep: combined conv kernel --------------------------------
__global__ void prep_kernel(const float* __restrict__ A, const float* __restrict__ Bp,
                            const float* __restrict__ Cp, const float* __restrict__ cw)
{
    __shared__ float U[DU][NSTATE];
    __shared__ float gk[DU];
    __shared__ float sC[NSTATE];
    int tid = threadIdx.x;
    int e = blockIdx.x;
    if (tid < 32) {
        int i = tid & 15;
        float u = 1.f / (1.f + expf(-Bp[i]));
        for (int d = 0; d < DU; d++) {
            if (tid < 16) U[d][i] = u;
            float nu = 0.f;
            #pragma unroll
            for (int j = 0; j < 16; j++)
                nu += A[i*16 + j] * __shfl_sync(0xFFFFFFFFu, u, j);
            u = nu;
        }
    }
    if (tid < 16) sC[tid] = 1.f / (1.f + expf(-Cp[e*16 + tid]));
    __syncthreads();
    for (int d = tid; d < DU; d += blockDim.x) {
        float s = 0.f;
        #pragma unroll
        for (int i = 0; i < 16; i++) s += sC[i] * U[d][i];
        gk[d] = s;
    }
    __syncthreads();
    for (int dd = tid; dd < DK; dd += blockDim.x) {
        float s = 0.f;
        #pragma unroll
        for (int d1 = 0; d1 < 4; d1++) {
            int d2 = dd - d1;
            if (d2 >= 0 && d2 < DU) s += cw[e*4 + (3 - d1)] * gk[d2];
        }
        g_K[e*DK + dd] = s;
    }
}

// ---------- row L2-normalize -> pre-split fp16 hi/lo planes (vectorized) ----
__global__ void norm_kernel(const float* __restrict__ xp,
                            __half* __restrict__ xh, __half* __restrict__ xl)
{
    int lane = threadIdx.x & 31;
    int row = blockIdx.x * 8 + (threadIdx.x >> 5);
    const float4* p4 = (const float4*)(xp + (size_t)row * EE);   // 84 float4
    float s = 0.f;
    float4 buf[3];
    #pragma unroll
    for (int i = 0; i < 3; i++) {
        int idx = lane + 32 * i;
        if (idx < 84) {
            float4 v = p4[idx];
            buf[i] = v;
            s += v.x*v.x + v.y*v.y + v.z*v.z + v.w*v.w;
        }
    }
    #pragma unroll
    for (int o = 16; o > 0; o >>= 1) s += __shfl_xor_sync(0xFFFFFFFFu, s, o);
    float inv = 1.f / fmaxf(sqrtf(s), 1e-12f);
    __half2* h2 = (__half2*)(xh + (size_t)row * EE);
    __half2* l2 = (__half2*)(xl + (size_t)row * EE);
    #pragma unroll
    for (int i = 0; i < 3; i++) {
        int idx = lane + 32 * i;
        if (idx < 84) {
            float4 v = buf[i];
            v.x *= inv; v.y *= inv; v.z *= inv; v.w *= inv;
            __half ha, la, hb, lb, hc, lc, hd, ld;
            f16_split(v.x, ha, la);
            f16_split(v.y, hb, lb);
            f16_split(v.z, hc, lc);
            f16_split(v.w, hd, ld);
            h2[idx*2 + 0] = __halves2half2(ha, hb);
            h2[idx*2 + 1] = __halves2half2(hc, hd);
            l2[idx*2 + 0] = __halves2half2(la, lb);
            l2[idx*2 + 1] = __halves2half2(lc, ld);
        }
    }
}

// ---------------- attention (float4 loads, fp16 att output) -----------------
__global__ void attn_kernel(const float* __restrict__ qkv,
                            __half* __restrict__ att, float* __restrict__ imp)
{
    __shared__ float sq[4][E3];
    __shared__ float sc[4][36];
    __shared__ int   gb[4][NH];
    int wid = threadIdx.x >> 5, lane = threadIdx.x & 31;
    int n = blockIdx.x * 4 + wid;
    const float4* row4 = (const float4*)(qkv + (size_t)n * E3);   // 252 float4
    float4* s4 = (float4*)sq[wid];
    #pragma unroll
    for (int i = 0; i < 8; i++) {
        int idx = lane + 32 * i;
        if (idx < 252) s4[idx] = row4[idx];
    }
    float* s = sq[wid];
    __syncwarp();
    for (int p = lane; p < 36; p += 32) {
        int h = p / 6, g = p - h*6;
        const float* qp = s + h*HDIM;
        const float* kp = s + EE + g*HDIM;
        float d = 0.f;
        #pragma unroll
        for (int t = 0; t < HDIM; t++) d += qp[t] * kp[t];
        sc[wid][p] = d;
    }
    __syncwarp();
    if (lane < NH) {
        float best = sc[wid][lane*6]; int bg = 0;
        #pragma unroll
        for (int g = 1; g < 6; g++) {
            float v = sc[wid][lane*6 + g];
            if (v > best) { best = v; bg = g; }   // strict > : jax tie -> lowest idx
        }
        gb[wid][lane] = bg;
    }
    __syncwarp();
    float acc = 0.f;
    for (int e = lane; e < EE; e += 32) {
        int h = e % NH, d = e / NH;
        float v = s[2*EE + gb[wid][h]*HDIM + d];
        att[(size_t)n*EE + e] = __float2half_rn(v);   // fp16: conv-only consumer
        acc += v*v;                                   // imp stays fp32
    }
    #pragma unroll
    for (int o = 16; o > 0; o >>= 1) acc += __shfl_xor_sync(0xFFFFFFFFu, acc, o);
    if (lane == 0) imp[n] = sqrtf(acc);
}

// ---------------- inverse index clear ----------------------------------------
__global__ void inv_clear_kernel()
{
    int i = blockIdx.x * 1024 + threadIdx.x;
    g_inv[i] = -1;
}

// ---------------- top-819 per batch + inverse map ----------------------------
__global__ void topk_kernel(const float* __restrict__ imp, int* __restrict__ idxout)
{
    __shared__ unsigned long long key[LL];
    int b = blockIdx.x;
    for (int i = threadIdx.x; i < LL; i += blockDim.x) {
        unsigned fb = __float_as_uint(imp[b*LL + i]);
        key[i] = ((unsigned long long)(0xFFFFFFFFu - fb) << 32) | (unsigned)i;
    }
    __syncthreads();
    for (int k = 2; k <= LL; k <<= 1)
        for (int j = k >> 1; j > 0; j >>= 1) {
            for (int i = threadIdx.x; i < LL; i += blockDim.x) {
                int ixj = i ^ j;
                if (ixj > i) {
                    bool up = ((i & k) == 0);
                    unsigned long long a = key[i], c = key[ixj];
                    if ((a > c) == up) { key[i] = c; key[ixj] = a; }
                }
            }
            __syncthreads();
        }
    for (int i = threadIdx.x; i < KC; i += blockDim.x) {
        int pos = (int)(key[i] & 0xFFFFFFFFu);
        idxout[b*KC + i] = pos;
        g_inv[b*LL + pos] = b*KC + i;     // global xproc row
    }
}

// -------- fused gather + 67-tap causal conv -> fp16 ys (hi only) ------------
__global__ void __launch_bounds__(224) conv_kernel(const __half* __restrict__ att,
                                                   const int* __restrict__ idx,
                                                   __half* __restrict__ ysh)
{
    const int ET = 56, JT = 64, WIN = JT + DK - 1;
    __shared__ float sp[ET][WIN + 1];
    __shared__ float Ks[ET][DK + 1];
    __shared__ int   sidx[WIN];
    int et = blockIdx.x, jt = blockIdx.y, b = blockIdx.z;
    int e0 = et * ET, j0 = jt * JT;
    int tid = threadIdx.x;

    for (int w = tid; w < WIN; w += 224) {
        int j = j0 - (DK - 1) + w;
        sidx[w] = (j >= 0 && j < KC) ? idx[b*KC + j] : -1;
    }
    for (int i = tid; i < ET*DK; i += 224) {
        int ee = i / DK, d = i - ee*DK;
        Ks[ee][d] = g_K[(e0 + ee)*DK + d];
    }
    __syncthreads();
    for (int i = tid; i < WIN*ET; i += 224) {
        int w = i / ET, ee = i - w*ET;
        int pos = sidx[w];
        sp[ee][w] = (pos >= 0) ? __half2float(att[((size_t)b*LL + pos)*EE + e0 + ee]) : 0.f;
    }
    __syncthreads();

    int ee = tid % ET, jg = tid / ET;
    float acc[16];
    #pragma unroll
    for (int t = 0; t < 16; t++) acc[t] = 0.f;
    int wbase = (DK - 1) + jg*16;
    for (int d = 0; d < DK; d++) {
        float kv = Ks[ee][d];
        #pragma unroll
        for (int t = 0; t < 16; t++)
            acc[t] += kv * sp[ee][wbase + t - d];
    }
    #pragma unroll
    for (int t = 0; t < 16; t++) {
        int j = j0 + jg*16 + t;
        if (j < KC)
            ysh[((size_t)b*KC + j)*EE + e0 + ee] = __float2half_rn(acc[t]);
    }
}

// ------------- fused output: out = x + (selected ? xproc : 0) ---------------
__global__ void out_kernel(const float4* __restrict__ x,
                           const float4* __restrict__ xproc,
                           float4* __restrict__ out)
{
    int row = blockIdx.x;                  // 0..NN-1
    int j = g_inv[row];
    const float4* xr = x + (size_t)row * 128;
    float4* o = out + (size_t)row * 128;
    int c = threadIdx.x;                   // 128 threads, one float4 each
    float4 v = xr[c];
    if (j >= 0) {
        float4 p = xproc[(size_t)j * 128 + c];
        v.x += p.x; v.y += p.y; v.z += p.z; v.w += p.w;
    }
    o[c] = v;
}

// ---------------- launch ----------------------------------------------------
extern "C" void kernel_launch(void* const* d_in, const int* in_sizes, int n_in,
                              void* d_out, int out_size)
{
    const float* x      = (const float*)d_in[0];
    const float* alpha  = (const float*)d_in[1];
    const float* dyt_w  = (const float*)d_in[2];
    const float* dyt_b  = (const float*)d_in[3];
    const float* W_in   = (const float*)d_in[4];
    const float* b_in   = (const float*)d_in[5];
    const float* W_qkv  = (const float*)d_in[6];
    const float* b_qkv  = (const float*)d_in[7];
    const float* conv_w = (const float*)d_in[8];
    const float* A      = (const float*)d_in[9];
    const float* Bp     = (const float*)d_in[10];
    const float* Cp     = (const float*)d_in[11];
    const float* W_out  = (const float*)d_in[12];
    const float* b_out  = (const float*)d_in[13];
    float* out = (float*)d_out;

    float *xp, *qkv, *imp, *xproc;
    __half *att, *wh, *wl, *xph, *xpl, *ysh;
    int *idx;
    cudaGetSymbolAddress((void**)&xp,    g_xp);
    cudaGetSymbolAddress((void**)&qkv,   g_qkv);
    cudaGetSymbolAddress((void**)&att,   g_att);
    cudaGetSymbolAddress((void**)&imp,   g_imp);
    cudaGetSymbolAddress((void**)&idx,   g_idx);
    cudaGetSymbolAddress((void**)&xproc, g_xproc);
    cudaGetSymbolAddress((void**)&wh,    g_Wh);
    cudaGetSymbolAddress((void**)&wl,    g_Wl);
    cudaGetSymbolAddress((void**)&xph,   g_xph);
    cudaGetSymbolAddress((void**)&xpl,   g_xpl);
    cudaGetSymbolAddress((void**)&ysh,   g_ysh);

    const int SM_M1  = (2*128*36 + 2*128*20 + 2*2*112*20) * 4;   // 93184
    const int SM_M0A = (2*2*128*20 + 2*2*112*20) * 4;            // 76800
    const int SM_HB  = (2*128*20 + 2*128*20) * 4;                // 40960 (hi-only)
    cudaFuncSetAttribute(mma_gemm<112,1,0>, cudaFuncAttributeMaxDynamicSharedMemorySize, SM_M1);
    cudaFuncSetAttribute(mma_gemm<112,0,0>, cudaFuncAttributeMaxDynamicSharedMemorySize, SM_M0A);
    cudaFuncSetAttribute(mma_gemm<128,0,1>, cudaFuncAttributeMaxDynamicSharedMemorySize, SM_HB);

    // launch order: qkv GEMM at capture index 3 (matches ncu -s 5 -c 1 slot)
    // 0) all weight planes: transpose + fp16 split
    wsplit_t_kernel<<<dim3(16, 32, 3), dim3(32, 8)>>>(W_in, W_qkv, W_out, wh, wl);
    // 1) xp = dyt(x) @ W_in + b_in   [32768,512]x[512,336]  (MODE1, 3-pass)
    mma_gemm<112,1,0><<<dim3(3, NN/128), 256, SM_M1>>>(x, nullptr, nullptr,
                                                       wh + OFF_WIN, wl + OFF_WIN,
                                                       b_in, xp, NN, EE, DIMC,
                                                       alpha, dyt_w, dyt_b);
    // 2) row-normalize -> pre-split xpn planes (vectorized)
    norm_kernel<<<NN/8, 256>>>(xp, xph, xpl);
    // 3) qkv = xpn @ W_qkv + b_qkv  [32768,336]x[336,1008]  (MODE0, 3-pass)
    mma_gemm<112,0,0><<<dim3(9, NN/128), 256, SM_M0A>>>(nullptr, xph, xpl,
                                                        wh + OFF_WQKV, wl + OFF_WQKV,
                                                        b_qkv, qkv, NN, E3, EE,
                                                        alpha, dyt_w, dyt_b);
    // 4) scan->conv kernel precompute + inverse-map clear
    prep_kernel<<<EE, 128>>>(A, Bp, Cp, conv_w);
    inv_clear_kernel<<<NN/1024, 1024>>>();
    // 5) sparse attention (kh=1 -> argmax gather) + importance
    attn_kernel<<<NN/4, 128>>>(qkv, att, imp);
    // 6) exact sorted top-819 per batch (+ inverse map)
    topk_kernel<<<BB, 1024>>>(imp, idx);
    // 7) gather + combined dconv*scan causal convolution -> fp16 ys
    conv_kernel<<<dim3(EE/56, (KC + 63)/64, BB), 224>>>(att, idx, ysh);
    // 8) xproc = ys @ W_out + b_out  [6552,336]x[336,512]  (pure fp16, 1-pass)
    mma_gemm<128,0,1><<<dim3(4, (BB*KC + 127)/128), 256, SM_HB>>>(nullptr, ysh, nullptr,
                                                                  wh + OFF_WOUT, nullptr,
                                                                  b_out, xproc, BB*KC, DIMC, EE,
                                                                  alpha, dyt_w, dyt_b);
    // 9) fused residual + scatter
    out_kernel<<<NN, 128>>>((const float4*)x, (const float4*)xproc, (float4*)out);
}